// round 11
// baseline (speedup 1.0000x reference)
#include <cuda_runtime.h>
#include <cuda_bf16.h>

#define BB   16
#define NN   2048
#define FIN  128
#define FO   64
#define TI   128
#define TJ   64
#define SPLITS 4
#define NT   (NN / SPLITS / TJ)   // 8
#define ALPHA 0.2f

// dynamic smem layout (bytes) for attn kernel
#define SM_ADJ  0          // adj tile [128 rows x 256B], chunk-swizzled, halves kb0-3 | kb4-7
#define SM_WH   32768      // wh tf32 [2][64 rows x 256B], chunk-swizzled
#define SM_FJ   65536      // fj [2][64 floats]
#define SM_TOTAL 66048

// ---- scratch ----
__device__ float    g_Wh[BB * NN * FO];
__device__ float    g_fi[BB * NN];
__device__ float    g_fj[BB * NN];
__device__ unsigned g_WhT[BB * FO * NN];            // tf32 bits, [b][o][j]
__device__ float    g_part[SPLITS * BB * NN * FO];
__device__ float    g_rsum[SPLITS * BB * NN];

// ---- f32x2 helpers (wh kernel) ----
__device__ __forceinline__ void fma2(unsigned long long& d, unsigned long long a, unsigned long long b) {
    asm("fma.rn.f32x2 %0, %1, %2, %0;" : "+l"(d) : "l"(a), "l"(b));
}
__device__ __forceinline__ unsigned long long pack2(float x, float y) {
    unsigned long long r; asm("mov.b64 %0, {%1, %2};" : "=l"(r) : "f"(x), "f"(y)); return r;
}
__device__ __forceinline__ float2 unpack2(unsigned long long v) {
    float2 r; asm("mov.b64 {%0, %1}, %2;" : "=f"(r.x), "=f"(r.y) : "l"(v)); return r;
}

// ---- cp.async ----
__device__ __forceinline__ void cpasync16(unsigned s, const void* g) {
    asm volatile("cp.async.cg.shared.global [%0], [%1], 16;" :: "r"(s), "l"(g) : "memory");
}
__device__ __forceinline__ void cpasync_commit() { asm volatile("cp.async.commit_group;" ::: "memory"); }
__device__ __forceinline__ void cpasync_wait_all() {
    asm volatile("cp.async.wait_group 0;" ::: "memory");
}

// ---- tf32 tensor-core (base ISA sm_80+) ----
__device__ __forceinline__ void mma_tf32(float* d, const unsigned* a, unsigned b0, unsigned b1) {
    asm volatile("mma.sync.aligned.m16n8k8.row.col.f32.tf32.tf32.f32 "
                 "{%0,%1,%2,%3}, {%4,%5,%6,%7}, {%8,%9}, {%0,%1,%2,%3};"
                 : "+f"(d[0]), "+f"(d[1]), "+f"(d[2]), "+f"(d[3])
                 : "r"(a[0]), "r"(a[1]), "r"(a[2]), "r"(a[3]), "r"(b0), "r"(b1));
}
__device__ __forceinline__ unsigned to_tf32(float f) {
    unsigned r; asm("cvt.rna.tf32.f32 %0, %1;" : "=r"(r) : "f"(f)); return r;
}

// ============================================================
// Kernel 1: Wh = h @ W (+ masked f_i, f_j)
// ============================================================
__global__ __launch_bounds__(256)
void gat_wh_kernel(const float* __restrict__ h, const float* __restrict__ W,
                   const float* __restrict__ a, const float* __restrict__ mask) {
    __shared__ float h_s[32 * FIN];
    __shared__ float W_s[FIN * FO];

    int tid = threadIdx.x;
    size_t base = (size_t)blockIdx.x * 32;
    {
        const float4* hsrc = (const float4*)(h + base * FIN);
        float4* hdst = (float4*)h_s;
        #pragma unroll
        for (int r = 0; r < 4; r++) hdst[r * 256 + tid] = hsrc[r * 256 + tid];
        const float4* wsrc = (const float4*)W;
        float4* wdst = (float4*)W_s;
        #pragma unroll
        for (int r = 0; r < 8; r++) wdst[r * 256 + tid] = wsrc[r * 256 + tid];
    }
    __syncthreads();

    int r = tid >> 4, og = tid & 15;
    unsigned long long acc0 = 0, acc1 = 0, acc2 = 0, acc3 = 0;
    const float* hrowA = h_s + r * FIN;
    const float* hrowB = h_s + (r + 16) * FIN;
    #pragma unroll 4
    for (int k = 0; k < FIN; k += 4) {
        float4 ha = *(const float4*)(hrowA + k);
        float4 hb = *(const float4*)(hrowB + k);
        #pragma unroll
        for (int t = 0; t < 4; t++) {
            float va = (t == 0) ? ha.x : (t == 1) ? ha.y : (t == 2) ? ha.z : ha.w;
            float vb = (t == 0) ? hb.x : (t == 1) ? hb.y : (t == 2) ? hb.z : hb.w;
            ulonglong2 w = *(const ulonglong2*)(W_s + (k + t) * FO + og * 4);
            unsigned long long va2 = pack2(va, va), vb2 = pack2(vb, vb);
            fma2(acc0, va2, w.x); fma2(acc1, va2, w.y);
            fma2(acc2, vb2, w.x); fma2(acc3, vb2, w.y);
        }
    }
    int o = og * 4;
    #pragma unroll
    for (int half = 0; half < 2; half++) {
        float2 p01 = unpack2(half ? acc2 : acc0);
        float2 p23 = unpack2(half ? acc3 : acc1);
        size_t row = base + r + half * 16;
        ((float4*)(g_Wh + row * FO))[og] = make_float4(p01.x, p01.y, p23.x, p23.y);
        float ps = p01.x * a[o]      + p01.y * a[o + 1]      + p23.x * a[o + 2]      + p23.y * a[o + 3];
        float pd = p01.x * a[FO + o] + p01.y * a[FO + o + 1] + p23.x * a[FO + o + 2] + p23.y * a[FO + o + 3];
        #pragma unroll
        for (int off = 8; off >= 1; off >>= 1) {
            ps += __shfl_down_sync(0xffffffffu, ps, off, 16);
            pd += __shfl_down_sync(0xffffffffu, pd, off, 16);
        }
        if (og == 0) {
            bool ok = mask[row] > 0.f;
            g_fi[row] = ok ? ps : -1e30f;
            g_fj[row] = ok ? pd : -1e30f;
        }
    }
}

// ============================================================
// Kernel 1b: WhT -> tf32 bits, n-major: g_WhT[b][o][j]
// ============================================================
__global__ __launch_bounds__(256)
void gat_wht_kernel() {
    __shared__ float tile[64][68];
    int tid = threadIdx.x;
    int j0 = blockIdx.x * 64;
    int b  = blockIdx.y;
    const float4* src = (const float4*)(g_Wh + (size_t)b * NN * FO + (size_t)j0 * FO);
    #pragma unroll
    for (int k = 0; k < 4; k++) {
        int idx = k * 256 + tid;
        int r = idx >> 4, c4 = idx & 15;
        float4 v = src[idx];
        tile[r][c4 * 4 + 0] = v.x; tile[r][c4 * 4 + 1] = v.y;
        tile[r][c4 * 4 + 2] = v.z; tile[r][c4 * 4 + 3] = v.w;
    }
    __syncthreads();
    int o = tid >> 2, cc = tid & 3;   // cc covers 16 j
    unsigned ov[16];
    #pragma unroll
    for (int u = 0; u < 16; u++)
        ov[u] = to_tf32(tile[cc * 16 + u][o]);
    size_t ob = (size_t)b * FO * NN + (size_t)o * NN + j0 + cc * 16;
    #pragma unroll
    for (int q = 0; q < 4; q++)
        *(uint4*)(g_WhT + ob + q * 4) = make_uint4(ov[4*q], ov[4*q+1], ov[4*q+2], ov[4*q+3]);
}

// ============================================================
// Kernel 2: attention, single-pass tf32 mma, fragment-direct A.
// 128 threads / 4 warps; warp w owns rows 32w..32w+31, N=64.
// Thread computes exactly its own A-fragment edges (4 rows x 16 cols).
// ============================================================
__device__ __forceinline__ void load_adj_half(unsigned sbase, const float* adj_row,
                                              int t, int h, int tid) {
    unsigned dstrow = sbase + SM_ADJ + (unsigned)tid * 256;
    const float* src = adj_row + t * TJ;
    #pragma unroll
    for (int k = 0; k < 8; k++) {
        int cc = h * 8 + k;
        cpasync16(dstrow + ((unsigned)(cc ^ (tid & 7)) << 4), src + cc * 4);
    }
}
__device__ __forceinline__ void load_wh_tile(unsigned sbase, int buf, const unsigned* wht_g,
                                             const float* fj_g, int jt, int tid) {
    #pragma unroll
    for (int k = 0; k < 8; k++) {
        int idx = tid + k * 128;              // 0..1023
        int o = idx >> 4, cc = idx & 15;
        cpasync16(sbase + SM_WH + buf * 16384 + o * 256 + ((unsigned)(cc ^ (o & 7)) << 4),
                  wht_g + (size_t)o * NN + jt * TJ + cc * 4);
    }
    if (tid < 16)
        cpasync16(sbase + SM_FJ + buf * 256 + tid * 16, fj_g + jt * TJ + tid * 4);
}

__global__ __launch_bounds__(128, 3)
void gat_attn_tf32(const float* __restrict__ adj,
                   float* __restrict__ part, float* __restrict__ rsum) {
    extern __shared__ char smem[];
    unsigned sbase = (unsigned)__cvta_generic_to_shared(smem);
    const int tid = threadIdx.x;
    const int wid = tid >> 5, lane = tid & 31;
    const int l4 = lane >> 2, lm4 = lane & 3;
    const int b = blockIdx.y, s = blockIdx.z;
    const int i0 = blockIdx.x * TI;
    const int jbeg = s * (NN / SPLITS);

    const float* adj_r = adj + (size_t)b * NN * NN + (size_t)(i0 + tid) * NN + jbeg;
    const float* fj_g  = g_fj + b * NN + jbeg;
    const unsigned* wht_g = g_WhT + (size_t)b * FO * NN + jbeg;

    // 4 fi values: rows 32w + l4 + 8s (s = 2mb + r8)
    float fi[4];
    #pragma unroll
    for (int q = 0; q < 4; q++) fi[q] = g_fi[b * NN + i0 + 32 * wid + l4 + 8 * q];

    float dacc[2][8][4];
    #pragma unroll
    for (int mb = 0; mb < 2; mb++)
        #pragma unroll
        for (int nb = 0; nb < 8; nb++)
            #pragma unroll
            for (int z = 0; z < 4; z++) dacc[mb][nb][z] = 0.f;
    float sums[4] = {0.f, 0.f, 0.f, 0.f};

    // prologue: adj(0) both halves + wh(0)/fj(0)
    load_adj_half(sbase, adj_r, 0, 0, tid);
    load_adj_half(sbase, adj_r, 0, 1, tid);
    load_wh_tile(sbase, 0, wht_g, fj_g, 0, tid);
    cpasync_commit();

    const unsigned adjbase = sbase + SM_ADJ + (unsigned)(32 * wid + l4) * 256 + (unsigned)lm4 * 4;

    for (int t = 0; t < NT; t++) {
        int cbuf = t & 1;
        cpasync_wait_all();
        __syncthreads();     // adj(t)/wh(t)/fj(t) visible

        unsigned afrag[4][2][4];
        const float* fj_s = (const float*)(smem + SM_FJ + cbuf * 256);
        unsigned whb = sbase + SM_WH + cbuf * 16384;

        #pragma unroll
        for (int h = 0; h < 2; h++) {
            // ---- p-half: kb = 4h..4h+3, compute A-fragments in regs ----
            #pragma unroll
            for (int kk = 0; kk < 4; kk++) {
                int kb = 4 * h + kk;
                #pragma unroll
                for (int dd = 0; dd < 2; dd++) {
                    int c = 8 * kb + lm4 + 4 * dd;
                    float fjv = fj_s[c];
                    unsigned chunk = (unsigned)((2 * kb + dd) ^ l4) << 4;
                    #pragma unroll
                    for (int q = 0; q < 4; q++) {   // q = 2*mb + r8
                        float av = *(const float*)((const char*)smem +
                                    (adjbase - sbase) + (unsigned)(q * 8) * 256 + chunk);
                        float x = fi[q] + fjv;
                        float l = fmaxf(x, ALPHA * x);
                        float p = (av > 0.f) ? __expf(l) : 0.f;
                        sums[q] += p;
                        afrag[kk][q >> 1][2 * dd + (q & 1)] = to_tf32(p);
                    }
                }
            }
            __syncthreads();   // this adj half fully consumed by all warps
            if (t + 1 < NT) {
                load_adj_half(sbase, adj_r, t + 1, h, tid);
                if (h == 1) load_wh_tile(sbase, 1 - cbuf, wht_g, fj_g, t + 1, tid);
                cpasync_commit();
            }
            // ---- mma-half ----
            #pragma unroll
            for (int kk = 0; kk < 4; kk++) {
                int kb = 4 * h + kk;
                unsigned bv[8][2];
                #pragma unroll
                for (int n8 = 0; n8 < 8; n8++) {
                    unsigned rowoff = (unsigned)(8 * n8 + l4) * 256 + (unsigned)lm4 * 4;
                    bv[n8][0] = *(const unsigned*)(smem + (whb - sbase) + rowoff +
                                 ((unsigned)((2 * kb)     ^ l4) << 4));
                    bv[n8][1] = *(const unsigned*)(smem + (whb - sbase) + rowoff +
                                 ((unsigned)((2 * kb + 1) ^ l4) << 4));
                }
                #pragma unroll
                for (int mb = 0; mb < 2; mb++)
                    #pragma unroll
                    for (int n8 = 0; n8 < 8; n8++)
                        mma_tf32(dacc[mb][n8], afrag[kk][mb], bv[n8][0], bv[n8][1]);
            }
        }
    }

    // ---- rowsum butterfly over the 4-lane column group ----
    #pragma unroll
    for (int off = 1; off <= 2; off <<= 1)
        #pragma unroll
        for (int q = 0; q < 4; q++)
            sums[q] += __shfl_xor_sync(0xffffffffu, sums[q], off);
    size_t rowbase = (size_t)s * BB * NN + (size_t)b * NN + i0;
    rsum[rowbase + 32 * wid + l4 + 8 * lm4] = sums[lm4];

    // ---- epilogue: write partials ----
    #pragma unroll
    for (int mb = 0; mb < 2; mb++) {
        int r0 = 32 * wid + 16 * mb + l4;
        #pragma unroll
        for (int nb = 0; nb < 8; nb++) {
            int col = 8 * nb + 2 * lm4;
            *(float2*)(part + (rowbase + r0) * FO + col)     = make_float2(dacc[mb][nb][0], dacc[mb][nb][1]);
            *(float2*)(part + (rowbase + r0 + 8) * FO + col) = make_float2(dacc[mb][nb][2], dacc[mb][nb][3]);
        }
    }
}

// ============================================================
// Kernel 3: reduce splits, normalize, relu
// ============================================================
__global__ __launch_bounds__(256)
void gat_reduce_kernel(const float* __restrict__ part,
                       const float* __restrict__ rsum,
                       float* __restrict__ out) {
    int t = blockIdx.x * blockDim.x + threadIdx.x;
    int rowi = t >> 4;
    float rs = 0.f;
    #pragma unroll
    for (int s = 0; s < SPLITS; s++) rs += rsum[(size_t)s * BB * NN + rowi];
    float inv = (rs > 0.f) ? (1.f / rs) : 0.f;
    float4 v = make_float4(0.f, 0.f, 0.f, 0.f);
    #pragma unroll
    for (int s = 0; s < SPLITS; s++) {
        float4 pv = ((const float4*)part)[(size_t)s * BB * NN * 16 + t];
        v.x += pv.x; v.y += pv.y; v.z += pv.z; v.w += pv.w;
    }
    float4 o;
    o.x = fmaxf(v.x * inv, 0.f);
    o.y = fmaxf(v.y * inv, 0.f);
    o.z = fmaxf(v.z * inv, 0.f);
    o.w = fmaxf(v.w * inv, 0.f);
    ((float4*)out)[t] = o;
}

// ============================================================
extern "C" void kernel_launch(void* const* d_in, const int* in_sizes, int n_in,
                              void* d_out, int out_size) {
    const float *h = nullptr, *adj = nullptr, *mask = nullptr, *W = nullptr, *a = nullptr;
    for (int i = 0; i < n_in; i++) {
        switch (in_sizes[i]) {
            case BB * NN * FIN:  h    = (const float*)d_in[i]; break;
            case BB * NN * NN:   adj  = (const float*)d_in[i]; break;
            case BB * NN:        mask = (const float*)d_in[i]; break;
            case FIN * FO:       W    = (const float*)d_in[i]; break;
            case 2 * FO:         a    = (const float*)d_in[i]; break;
        }
    }
    float* out = (float*)d_out;
    float* part; cudaGetSymbolAddress((void**)&part, g_part);
    float* rsum; cudaGetSymbolAddress((void**)&rsum, g_rsum);

    static bool attr_set = false;
    if (!attr_set) {
        cudaFuncSetAttribute(gat_attn_tf32, cudaFuncAttributeMaxDynamicSharedMemorySize, SM_TOTAL);
        attr_set = true;
    }

    gat_wh_kernel<<<BB * NN / 32, 256>>>(h, W, a, mask);
    gat_wht_kernel<<<dim3(NN / 64, BB), 256>>>();
    gat_attn_tf32<<<dim3(NN / TI, BB, SPLITS), 128, SM_TOTAL>>>(adj, part, rsum);
    gat_reduce_kernel<<<BB * NN * 16 / 256, 256>>>(part, rsum, out);
}

// round 12
// speedup vs baseline: 1.2745x; 1.2745x over previous
#include <cuda_runtime.h>
#include <cuda_bf16.h>

#define BB   16
#define NN   2048
#define FIN  128
#define FO   64
#define TI   128
#define TJ   64
#define SPLITS 4
#define NT   (NN / SPLITS / TJ)   // 8
#define ALPHA 0.2f

// dynamic smem layout (bytes) for attn kernel
#define SM_P    0          // p tf32 [128 rows x 256B], chunk-swizzled
#define SM_WH   32768      // wh tf32 [2][64 rows x 256B], chunk-swizzled
#define SM_FJ   65536      // fj [2][64 floats]
#define SM_TOTAL 66048

// ---- scratch ----
__device__ float    g_Wh[BB * NN * FO];
__device__ float    g_fi[BB * NN];
__device__ float    g_fj[BB * NN];
__device__ unsigned g_WhT[BB * FO * NN];            // tf32 bits, [b][o][j] (n-major)
__device__ float    g_part[SPLITS * BB * NN * FO];
__device__ float    g_rsum[SPLITS * BB * NN];

// ---- f32x2 helpers (wh kernel) ----
__device__ __forceinline__ void fma2(unsigned long long& d, unsigned long long a, unsigned long long b) {
    asm("fma.rn.f32x2 %0, %1, %2, %0;" : "+l"(d) : "l"(a), "l"(b));
}
__device__ __forceinline__ unsigned long long pack2(float x, float y) {
    unsigned long long r; asm("mov.b64 %0, {%1, %2};" : "=l"(r) : "f"(x), "f"(y)); return r;
}
__device__ __forceinline__ float2 unpack2(unsigned long long v) {
    float2 r; asm("mov.b64 {%0, %1}, %2;" : "=f"(r.x), "=f"(r.y) : "l"(v)); return r;
}

// ---- cp.async ----
__device__ __forceinline__ void cpasync16(unsigned s, const void* g) {
    asm volatile("cp.async.cg.shared.global [%0], [%1], 16;" :: "r"(s), "l"(g) : "memory");
}
__device__ __forceinline__ void cpasync_commit() { asm volatile("cp.async.commit_group;" ::: "memory"); }
__device__ __forceinline__ void cpasync_wait_all() {
    asm volatile("cp.async.wait_group 0;" ::: "memory");
}

// ---- tensor-core (base ISA) ----
__device__ __forceinline__ void ldm_x4(unsigned* d, unsigned saddr) {
    asm volatile("ldmatrix.sync.aligned.m8n8.x4.shared.b16 {%0,%1,%2,%3}, [%4];"
                 : "=r"(d[0]), "=r"(d[1]), "=r"(d[2]), "=r"(d[3]) : "r"(saddr));
}
__device__ __forceinline__ void mma_tf32(float* d, const unsigned* a, unsigned b0, unsigned b1) {
    asm volatile("mma.sync.aligned.m16n8k8.row.col.f32.tf32.tf32.f32 "
                 "{%0,%1,%2,%3}, {%4,%5,%6,%7}, {%8,%9}, {%0,%1,%2,%3};"
                 : "+f"(d[0]), "+f"(d[1]), "+f"(d[2]), "+f"(d[3])
                 : "r"(a[0]), "r"(a[1]), "r"(a[2]), "r"(a[3]), "r"(b0), "r"(b1));
}
__device__ __forceinline__ unsigned to_tf32(float f) {
    unsigned r; asm("cvt.rna.tf32.f32 %0, %1;" : "=r"(r) : "f"(f)); return r;
}

// ============================================================
// Kernel 1: Wh = h @ W (+ masked f_i, f_j)
// ============================================================
__global__ __launch_bounds__(256)
void gat_wh_kernel(const float* __restrict__ h, const float* __restrict__ W,
                   const float* __restrict__ a, const float* __restrict__ mask) {
    __shared__ float h_s[32 * FIN];
    __shared__ float W_s[FIN * FO];

    int tid = threadIdx.x;
    size_t base = (size_t)blockIdx.x * 32;
    {
        const float4* hsrc = (const float4*)(h + base * FIN);
        float4* hdst = (float4*)h_s;
        #pragma unroll
        for (int r = 0; r < 4; r++) hdst[r * 256 + tid] = hsrc[r * 256 + tid];
        const float4* wsrc = (const float4*)W;
        float4* wdst = (float4*)W_s;
        #pragma unroll
        for (int r = 0; r < 8; r++) wdst[r * 256 + tid] = wsrc[r * 256 + tid];
    }
    __syncthreads();

    int r = tid >> 4, og = tid & 15;
    unsigned long long acc0 = 0, acc1 = 0, acc2 = 0, acc3 = 0;
    const float* hrowA = h_s + r * FIN;
    const float* hrowB = h_s + (r + 16) * FIN;
    #pragma unroll 4
    for (int k = 0; k < FIN; k += 4) {
        float4 ha = *(const float4*)(hrowA + k);
        float4 hb = *(const float4*)(hrowB + k);
        #pragma unroll
        for (int t = 0; t < 4; t++) {
            float va = (t == 0) ? ha.x : (t == 1) ? ha.y : (t == 2) ? ha.z : ha.w;
            float vb = (t == 0) ? hb.x : (t == 1) ? hb.y : (t == 2) ? hb.z : hb.w;
            ulonglong2 w = *(const ulonglong2*)(W_s + (k + t) * FO + og * 4);
            unsigned long long va2 = pack2(va, va), vb2 = pack2(vb, vb);
            fma2(acc0, va2, w.x); fma2(acc1, va2, w.y);
            fma2(acc2, vb2, w.x); fma2(acc3, vb2, w.y);
        }
    }
    int o = og * 4;
    #pragma unroll
    for (int half = 0; half < 2; half++) {
        float2 p01 = unpack2(half ? acc2 : acc0);
        float2 p23 = unpack2(half ? acc3 : acc1);
        size_t row = base + r + half * 16;
        ((float4*)(g_Wh + row * FO))[og] = make_float4(p01.x, p01.y, p23.x, p23.y);
        float ps = p01.x * a[o]      + p01.y * a[o + 1]      + p23.x * a[o + 2]      + p23.y * a[o + 3];
        float pd = p01.x * a[FO + o] + p01.y * a[FO + o + 1] + p23.x * a[FO + o + 2] + p23.y * a[FO + o + 3];
        #pragma unroll
        for (int off = 8; off >= 1; off >>= 1) {
            ps += __shfl_down_sync(0xffffffffu, ps, off, 16);
            pd += __shfl_down_sync(0xffffffffu, pd, off, 16);
        }
        if (og == 0) {
            bool ok = mask[row] > 0.f;
            g_fi[row] = ok ? ps : -1e30f;
            g_fj[row] = ok ? pd : -1e30f;
        }
    }
}

// ============================================================
// Kernel 1b: WhT -> tf32 bits, n-major: g_WhT[b][o][j]
// ============================================================
__global__ __launch_bounds__(256)
void gat_wht_kernel() {
    __shared__ float tile[64][68];
    int tid = threadIdx.x;
    int j0 = blockIdx.x * 64;
    int b  = blockIdx.y;
    const float4* src = (const float4*)(g_Wh + (size_t)b * NN * FO + (size_t)j0 * FO);
    #pragma unroll
    for (int k = 0; k < 4; k++) {
        int idx = k * 256 + tid;
        int r = idx >> 4, c4 = idx & 15;
        float4 v = src[idx];
        tile[r][c4 * 4 + 0] = v.x; tile[r][c4 * 4 + 1] = v.y;
        tile[r][c4 * 4 + 2] = v.z; tile[r][c4 * 4 + 3] = v.w;
    }
    __syncthreads();
    int o = tid >> 2, cc = tid & 3;   // cc covers 16 j
    unsigned ov[16];
    #pragma unroll
    for (int u = 0; u < 16; u++)
        ov[u] = to_tf32(tile[cc * 16 + u][o]);
    size_t ob = (size_t)b * FO * NN + (size_t)o * NN + j0 + cc * 16;
    #pragma unroll
    for (int q = 0; q < 4; q++)
        *(uint4*)(g_WhT + ob + q * 4) = make_uint4(ov[4*q], ov[4*q+1], ov[4*q+2], ov[4*q+3]);
}

// ============================================================
// Kernel 2: attention. R9 structure, tf32 datapath via ldmatrix.
// 128 threads / 4 warps; warp w owns rows 32w..32w+31, N=64.
// p-stage: thread = i-row, 64 edges, exact fp32 rowsum, tf32 store.
// ============================================================
__device__ __forceinline__ void load_wh_tile(unsigned sbase, int buf, const unsigned* wht_g,
                                             const float* fj_g, int jt, int tid) {
    #pragma unroll
    for (int k = 0; k < 8; k++) {
        int idx = tid + k * 128;              // 0..1023
        int o = idx >> 4, cc = idx & 15;
        cpasync16(sbase + SM_WH + buf * 16384 + o * 256 + ((unsigned)(cc ^ (o & 7)) << 4),
                  wht_g + (size_t)o * NN + jt * TJ + cc * 4);
    }
    if (tid < 16)
        cpasync16(sbase + SM_FJ + buf * 256 + tid * 16, fj_g + jt * TJ + tid * 4);
}

__global__ __launch_bounds__(128, 3)
void gat_attn_tf32(const float* __restrict__ adj,
                   float* __restrict__ part, float* __restrict__ rsum) {
    extern __shared__ char smem[];
    unsigned sbase = (unsigned)__cvta_generic_to_shared(smem);
    const int tid = threadIdx.x;
    const int wid = tid >> 5, lane = tid & 31;
    const int b = blockIdx.y, s = blockIdx.z;
    const int i0 = blockIdx.x * TI;
    const int jbeg = s * (NN / SPLITS);

    const float* adj_r = adj + (size_t)b * NN * NN + (size_t)(i0 + tid) * NN + jbeg;
    const float* fj_g  = g_fj + b * NN + jbeg;
    const float  fiv   = g_fi[b * NN + i0 + tid];
    const unsigned* wht_g = g_WhT + (size_t)b * FO * NN + jbeg;

    float dacc[2][8][4];
    #pragma unroll
    for (int mb = 0; mb < 2; mb++)
        #pragma unroll
        for (int nb = 0; nb < 8; nb++)
            #pragma unroll
            for (int z = 0; z < 4; z++) dacc[mb][nb][z] = 0.f;
    float rowsum = 0.f;

    // prologue: wh(0)/fj(0)
    load_wh_tile(sbase, 0, wht_g, fj_g, 0, tid);
    cpasync_commit();

    // ldmatrix per-lane addressing components (tf32 fragments):
    // A (p tile): row = base + (lane&15), k-quad select = lane>>4
    // B (wh tile): row = (lane&7) + ((lane>>4)<<3), k-quad select = (lane>>3)&1
    const int a_row = lane & 15;
    const int a_cs  = lane >> 4;
    const int b_row = (lane & 7) + ((lane >> 4) << 3);
    const int b_cs  = (lane >> 3) & 1;
    const int psw   = tid & 7;

    for (int t = 0; t < NT; t++) {
        int cbuf = t & 1;

        // adj first half: issued before the wait (latency under it)
        float4 av[8];
        {
            const float4* ap = (const float4*)(adj_r + t * TJ);
            #pragma unroll
            for (int k = 0; k < 8; k++) av[k] = ap[k];
        }

        cpasync_wait_all();
        __syncthreads();   // wh(t)/fj(t) visible; p(t-1) fully consumed

        // adj second half: issued now, hidden under first-half p-compute
        float4 av2[8];
        {
            const float4* ap = (const float4*)(adj_r + t * TJ);
            #pragma unroll
            for (int k = 0; k < 8; k++) av2[k] = ap[8 + k];
        }

        // ---- p-stage: 64 edges/thread, exact fp32 rowsum, tf32 store ----
        {
            const float4* fp = (const float4*)(smem + SM_FJ + cbuf * 256);
            #pragma unroll
            for (int g = 0; g < 16; g++) {
                float4 aa = (g < 8) ? av[g & 7] : av2[g & 7];
                float4 ff = fp[g];
                float x0 = fiv + ff.x, x1 = fiv + ff.y, x2 = fiv + ff.z, x3 = fiv + ff.w;
                float p0 = (aa.x > 0.f) ? __expf(fmaxf(x0, ALPHA * x0)) : 0.f;
                float p1 = (aa.y > 0.f) ? __expf(fmaxf(x1, ALPHA * x1)) : 0.f;
                float p2 = (aa.z > 0.f) ? __expf(fmaxf(x2, ALPHA * x2)) : 0.f;
                float p3 = (aa.w > 0.f) ? __expf(fmaxf(x3, ALPHA * x3)) : 0.f;
                rowsum += p0 + p1 + p2 + p3;
                uint4 pv = make_uint4(to_tf32(p0), to_tf32(p1), to_tf32(p2), to_tf32(p3));
                *(uint4*)(smem + SM_P + tid * 256 + ((unsigned)(g ^ psw) << 4)) = pv;
            }
        }
        __syncthreads();   // p(t) visible

        // prefetch wh(t+1): overlaps mma(t)
        if (t + 1 < NT) {
            load_wh_tile(sbase, 1 - cbuf, wht_g, fj_g, t + 1, tid);
            cpasync_commit();
        }

        // ---- mma stage: tf32 m16n8k8, fragments via ldmatrix ----
        unsigned whb = sbase + SM_WH + cbuf * 16384;
        #pragma unroll
        for (int kb = 0; kb < 8; kb++) {
            unsigned af[2][4];
            #pragma unroll
            for (int mb = 0; mb < 2; mb++) {
                int r = 32 * wid + 16 * mb + a_row;
                unsigned addr = sbase + SM_P + (unsigned)r * 256 +
                                ((unsigned)((2 * kb + a_cs) ^ (r & 7)) << 4);
                ldm_x4(af[mb], addr);
            }
            #pragma unroll
            for (int n16 = 0; n16 < 4; n16++) {
                int rn = 16 * n16 + b_row;
                unsigned addr = whb + (unsigned)rn * 256 +
                                ((unsigned)((2 * kb + b_cs) ^ (rn & 7)) << 4);
                unsigned q[4];
                ldm_x4(q, addr);
                #pragma unroll
                for (int mb = 0; mb < 2; mb++) {
                    mma_tf32(dacc[mb][2 * n16],     af[mb], q[0], q[1]);
                    mma_tf32(dacc[mb][2 * n16 + 1], af[mb], q[2], q[3]);
                }
            }
        }
    }

    // ---- epilogue ----
    size_t rowbase = (size_t)s * BB * NN + (size_t)b * NN + i0;
    rsum[rowbase + tid] = rowsum;
    const int l4 = lane >> 2, lm4 = lane & 3;
    #pragma unroll
    for (int mb = 0; mb < 2; mb++) {
        int r0 = 32 * wid + 16 * mb + l4;
        #pragma unroll
        for (int nb = 0; nb < 8; nb++) {
            int col = 8 * nb + 2 * lm4;
            *(float2*)(part + (rowbase + r0) * FO + col)     = make_float2(dacc[mb][nb][0], dacc[mb][nb][1]);
            *(float2*)(part + (rowbase + r0 + 8) * FO + col) = make_float2(dacc[mb][nb][2], dacc[mb][nb][3]);
        }
    }
}

// ============================================================
// Kernel 3: reduce splits, normalize, relu
// ============================================================
__global__ __launch_bounds__(256)
void gat_reduce_kernel(const float* __restrict__ part,
                       const float* __restrict__ rsum,
                       float* __restrict__ out) {
    int t = blockIdx.x * blockDim.x + threadIdx.x;
    int rowi = t >> 4;
    float rs = 0.f;
    #pragma unroll
    for (int s = 0; s < SPLITS; s++) rs += rsum[(size_t)s * BB * NN + rowi];
    float inv = (rs > 0.f) ? (1.f / rs) : 0.f;
    float4 v = make_float4(0.f, 0.f, 0.f, 0.f);
    #pragma unroll
    for (int s = 0; s < SPLITS; s++) {
        float4 pv = ((const float4*)part)[(size_t)s * BB * NN * 16 + t];
        v.x += pv.x; v.y += pv.y; v.z += pv.z; v.w += pv.w;
    }
    float4 o;
    o.x = fmaxf(v.x * inv, 0.f);
    o.y = fmaxf(v.y * inv, 0.f);
    o.z = fmaxf(v.z * inv, 0.f);
    o.w = fmaxf(v.w * inv, 0.f);
    ((float4*)out)[t] = o;
}

// ============================================================
extern "C" void kernel_launch(void* const* d_in, const int* in_sizes, int n_in,
                              void* d_out, int out_size) {
    const float *h = nullptr, *adj = nullptr, *mask = nullptr, *W = nullptr, *a = nullptr;
    for (int i = 0; i < n_in; i++) {
        switch (in_sizes[i]) {
            case BB * NN * FIN:  h    = (const float*)d_in[i]; break;
            case BB * NN * NN:   adj  = (const float*)d_in[i]; break;
            case BB * NN:        mask = (const float*)d_in[i]; break;
            case FIN * FO:       W    = (const float*)d_in[i]; break;
            case 2 * FO:         a    = (const float*)d_in[i]; break;
        }
    }
    float* out = (float*)d_out;
    float* part; cudaGetSymbolAddress((void**)&part, g_part);
    float* rsum; cudaGetSymbolAddress((void**)&rsum, g_rsum);

    static bool attr_set = false;
    if (!attr_set) {
        cudaFuncSetAttribute(gat_attn_tf32, cudaFuncAttributeMaxDynamicSharedMemorySize, SM_TOTAL);
        attr_set = true;
    }

    gat_wh_kernel<<<BB * NN / 32, 256>>>(h, W, a, mask);
    gat_wht_kernel<<<dim3(NN / 64, BB), 256>>>();
    gat_attn_tf32<<<dim3(NN / TI, BB, SPLITS), 128, SM_TOTAL>>>(adj, part, rsum);
    gat_reduce_kernel<<<BB * NN * 16 / 256, 256>>>(part, rsum, out);
}

// round 13
// speedup vs baseline: 1.5886x; 1.2465x over previous
#include <cuda_runtime.h>
#include <cuda_bf16.h>

#define BB   16
#define NN   2048
#define FIN  128
#define FO   64
#define TI   128
#define TJ   64
#define SPLITS 4
#define NT   (NN / SPLITS / TJ)   // 8
#define ALPHA 0.2f

// attn dynamic smem layout (bytes)
#define SM_PHI  0          // p hi  [128 x 128B]
#define SM_PLO  16384      // p lo
#define SM_ADJ  32768      // adj tile [128 rows x 256B], chunk-swizzled
#define SM_WHHI 65536      // wh hi [2][64 x 128B]
#define SM_WHLO 81920      // wh lo [2][64 x 128B]
#define SM_FJ   98304      // fj [2][64 floats]
#define SM_TOTAL 98816

#define WH_SMEM (64 * 1024)

// ---- scratch ----
__device__ float    g_fi[BB * NN];
__device__ float    g_fj[BB * NN];
__device__ unsigned g_WhT_hi[BB * FO * (NN / 2)];   // bf16x2 [b][o][j/2] (n-major)
__device__ unsigned g_WhT_lo[BB * FO * (NN / 2)];
__device__ float    g_part[SPLITS * BB * NN * FO];
__device__ float    g_rsum[SPLITS * BB * NN];

// ---- f32x2 helpers ----
__device__ __forceinline__ void fma2(unsigned long long& d, unsigned long long a, unsigned long long b) {
    asm("fma.rn.f32x2 %0, %1, %2, %0;" : "+l"(d) : "l"(a), "l"(b));
}
__device__ __forceinline__ unsigned long long pack2(float x, float y) {
    unsigned long long r; asm("mov.b64 %0, {%1, %2};" : "=l"(r) : "f"(x), "f"(y)); return r;
}
__device__ __forceinline__ float2 unpack2(unsigned long long v) {
    float2 r; asm("mov.b64 {%0, %1}, %2;" : "=f"(r.x), "=f"(r.y) : "l"(v)); return r;
}

// ---- cp.async ----
__device__ __forceinline__ void cpasync16(unsigned s, const void* g) {
    asm volatile("cp.async.cg.shared.global [%0], [%1], 16;" :: "r"(s), "l"(g) : "memory");
}
__device__ __forceinline__ void cpasync_commit() { asm volatile("cp.async.commit_group;" ::: "memory"); }
__device__ __forceinline__ void cpasync_wait_all() {
    asm volatile("cp.async.wait_group 0;" ::: "memory");
}

// ---- tensor-core (base ISA) ----
__device__ __forceinline__ void ldm_x4(unsigned* d, unsigned saddr) {
    asm volatile("ldmatrix.sync.aligned.m8n8.x4.shared.b16 {%0,%1,%2,%3}, [%4];"
                 : "=r"(d[0]), "=r"(d[1]), "=r"(d[2]), "=r"(d[3]) : "r"(saddr));
}
__device__ __forceinline__ void mma_bf16(float* d, const unsigned* a, unsigned b0, unsigned b1) {
    asm volatile("mma.sync.aligned.m16n8k16.row.col.f32.bf16.bf16.f32 "
                 "{%0,%1,%2,%3}, {%4,%5,%6,%7}, {%8,%9}, {%0,%1,%2,%3};"
                 : "+f"(d[0]), "+f"(d[1]), "+f"(d[2]), "+f"(d[3])
                 : "r"(a[0]), "r"(a[1]), "r"(a[2]), "r"(a[3]), "r"(b0), "r"(b1));
}

__device__ __forceinline__ unsigned pack_bf16x2(float lo_v, float hi_v) {
    unsigned r; asm("cvt.rn.bf16x2.f32 %0, %1, %2;" : "=r"(r) : "f"(hi_v), "f"(lo_v)); return r;
}
__device__ __forceinline__ void split2(float v0, float v1, unsigned& hi, unsigned& lo) {
    unsigned b0 = __float_as_uint(v0), b1 = __float_as_uint(v1);
    hi = (b0 >> 16) | (b1 & 0xFFFF0000u);
    float h0 = __uint_as_float(b0 & 0xFFFF0000u);
    float h1 = __uint_as_float(b1 & 0xFFFF0000u);
    lo = pack_bf16x2(v0 - h0, v1 - h1);
}

// ============================================================
// Kernel 1 (fused): Wh = h @ W, masked f_i/f_j, and WhT bf16
// hi/lo split-transpose — all in one pass. 64 rows/block,
// 4 rows/thread. No fp32 Wh ever hits gmem.
// ============================================================
__global__ __launch_bounds__(256)
void gat_wh_fused(const float* __restrict__ h, const float* __restrict__ W,
                  const float* __restrict__ a, const float* __restrict__ mask) {
    extern __shared__ float ws[];
    float* h_s = ws;              // 64*128 floats (32KB)
    float* W_s = ws + 64 * FIN;   // 128*64 floats (32KB)

    int tid = threadIdx.x;
    size_t base = (size_t)blockIdx.x * 64;

    {
        const float4* hsrc = (const float4*)(h + base * FIN);
        float4* hdst = (float4*)h_s;
        #pragma unroll
        for (int r = 0; r < 8; r++) hdst[r * 256 + tid] = hsrc[r * 256 + tid];
        const float4* wsrc = (const float4*)W;
        float4* wdst = (float4*)W_s;
        #pragma unroll
        for (int r = 0; r < 8; r++) wdst[r * 256 + tid] = wsrc[r * 256 + tid];
    }
    __syncthreads();

    int r = tid >> 4, og = tid & 15;
    unsigned long long acc[8];    // 4 rows x (2 ull = 4 floats)
    #pragma unroll
    for (int z = 0; z < 8; z++) acc[z] = 0ull;

    #pragma unroll 2
    for (int k = 0; k < FIN; k += 4) {
        float4 hv[4];
        #pragma unroll
        for (int q = 0; q < 4; q++)
            hv[q] = *(const float4*)(h_s + (r + 16 * q) * FIN + k);
        #pragma unroll
        for (int t = 0; t < 4; t++) {
            ulonglong2 w = *(const ulonglong2*)(W_s + (k + t) * FO + og * 4);
            #pragma unroll
            for (int q = 0; q < 4; q++) {
                float v = (t == 0) ? hv[q].x : (t == 1) ? hv[q].y : (t == 2) ? hv[q].z : hv[q].w;
                unsigned long long v2 = pack2(v, v);
                fma2(acc[2 * q],     v2, w.x);
                fma2(acc[2 * q + 1], v2, w.y);
            }
        }
    }

    // fi/fj + store Wh into transpose buffer (reuse h_s)
    int o = og * 4;
    float a_s0 = a[o],      a_s1 = a[o + 1],      a_s2 = a[o + 2],      a_s3 = a[o + 3];
    float a_d0 = a[FO + o], a_d1 = a[FO + o + 1], a_d2 = a[FO + o + 2], a_d3 = a[FO + o + 3];
    __syncthreads();          // done reading h_s; reuse as wt[64][65]
    float* wt = h_s;
    #pragma unroll
    for (int q = 0; q < 4; q++) {
        float2 p01 = unpack2(acc[2 * q]);
        float2 p23 = unpack2(acc[2 * q + 1]);
        int rowl = r + 16 * q;
        wt[rowl * 65 + o]     = p01.x;
        wt[rowl * 65 + o + 1] = p01.y;
        wt[rowl * 65 + o + 2] = p23.x;
        wt[rowl * 65 + o + 3] = p23.y;

        float ps = p01.x * a_s0 + p01.y * a_s1 + p23.x * a_s2 + p23.y * a_s3;
        float pd = p01.x * a_d0 + p01.y * a_d1 + p23.x * a_d2 + p23.y * a_d3;
        #pragma unroll
        for (int off = 8; off >= 1; off >>= 1) {
            ps += __shfl_down_sync(0xffffffffu, ps, off, 16);
            pd += __shfl_down_sync(0xffffffffu, pd, off, 16);
        }
        if (og == 0) {
            size_t row = base + rowl;
            bool ok = mask[row] > 0.f;
            g_fi[row] = ok ? ps : -1e30f;
            g_fj[row] = ok ? pd : -1e30f;
        }
    }
    __syncthreads();

    // split-transpose: thread (oo = tid>>2, q = tid&3) handles 8 j-pairs
    {
        int oo = tid >> 2, q = tid & 3;
        unsigned oh[8], ol[8];
        #pragma unroll
        for (int u = 0; u < 8; u++) {
            int j = 16 * q + 2 * u;
            split2(wt[j * 65 + oo], wt[(j + 1) * 65 + oo], oh[u], ol[u]);
        }
        int bb = (int)(base >> 11);
        int n0 = (int)(base & (NN - 1));
        size_t ob = (size_t)bb * FO * (NN / 2) + (size_t)oo * (NN / 2) + n0 / 2 + q * 8;
        *(uint4*)(g_WhT_hi + ob)     = make_uint4(oh[0], oh[1], oh[2], oh[3]);
        *(uint4*)(g_WhT_hi + ob + 4) = make_uint4(oh[4], oh[5], oh[6], oh[7]);
        *(uint4*)(g_WhT_lo + ob)     = make_uint4(ol[0], ol[1], ol[2], ol[3]);
        *(uint4*)(g_WhT_lo + ob + 4) = make_uint4(ol[4], ol[5], ol[6], ol[7]);
    }
}

// ============================================================
// Kernel 2: attention (champion structure + half-pipelining).
// 128 threads / 4 warps; warp w owns rows 32w..32w+31, N=64.
// ============================================================
__device__ __forceinline__ void load_wh_tile(unsigned sbase, int buf, const unsigned* hi_g,
                                             const unsigned* lo_g, const float* fj_g,
                                             int jt, int tid) {
    #pragma unroll
    for (int k = 0; k < 4; k++) {
        int idx = tid + k * 128;              // 0..511
        int o = idx >> 3, cc = idx & 7;
        unsigned co = (unsigned)((cc ^ (o & 7)) * 16);
        cpasync16(sbase + SM_WHHI + buf * 8192 + o * 128 + co,
                  hi_g + (size_t)o * (NN / 2) + jt * 32 + cc * 4);
        cpasync16(sbase + SM_WHLO + buf * 8192 + o * 128 + co,
                  lo_g + (size_t)o * (NN / 2) + jt * 32 + cc * 4);
    }
    if (tid < 16)
        cpasync16(sbase + SM_FJ + buf * 256 + tid * 16, fj_g + jt * TJ + tid * 4);
}

// adj tile: row tid (256B), 16 chunks of 16B, chunk-swizzled by (c ^ (tid&7))
__device__ __forceinline__ void load_adj_tile(unsigned sbase, const float* adj_row, int t, int tid) {
    unsigned dstrow = sbase + SM_ADJ + (unsigned)tid * 256;
    const float* src = adj_row + t * TJ;
    #pragma unroll
    for (int cchunk = 0; cchunk < 16; cchunk++)
        cpasync16(dstrow + ((unsigned)(cchunk ^ (tid & 7)) << 4), src + cchunk * 4);
}

__global__ __launch_bounds__(128)
void gat_attn_hmma(const float* __restrict__ adj,
                   float* __restrict__ part, float* __restrict__ rsum) {
    extern __shared__ char smem[];
    unsigned sbase = (unsigned)__cvta_generic_to_shared(smem);
    const int tid = threadIdx.x;
    const int wid = tid >> 5, lane = tid & 31;
    const int b = blockIdx.y, s = blockIdx.z;
    const int i0 = blockIdx.x * TI;
    const int jbeg = s * (NN / SPLITS);

    const float* adj_r = adj + (size_t)b * NN * NN + (size_t)(i0 + tid) * NN + jbeg;
    const float* fj_g  = g_fj + b * NN + jbeg;
    const float  fiv   = g_fi[b * NN + i0 + tid];
    const unsigned* whhi_g = g_WhT_hi + (size_t)b * FO * (NN / 2) + jbeg / 2;
    const unsigned* whlo_g = g_WhT_lo + (size_t)b * FO * (NN / 2) + jbeg / 2;

    float dacc[2][8][4];
    #pragma unroll
    for (int mb = 0; mb < 2; mb++)
        #pragma unroll
        for (int nb = 0; nb < 8; nb++)
            #pragma unroll
            for (int z = 0; z < 4; z++) dacc[mb][nb][z] = 0.f;
    float rowsum = 0.f;

    // prologue: adj(0) + wh(0) + fj(0)
    load_adj_tile(sbase, adj_r, 0, tid);
    load_wh_tile(sbase, 0, whhi_g, whlo_g, fj_g, 0, tid);
    cpasync_commit();

    const int a_roff = ((lane >> 3) & 1) * 8 + (lane & 7);
    const int a_cs   = lane >> 4;
    const int b_roff = ((lane >> 4) << 3) + (lane & 7);
    const int b_cs   = (lane >> 3) & 1;
    const int asw    = tid & 7;
    const char* arow = smem + SM_ADJ + tid * 256;

    for (int t = 0; t < NT; t++) {
        int c = t & 1;

        cpasync_wait_all();
        __syncthreads();   // adj(t)/wh(t)/fj(t) visible; p(t-1) fully consumed

        const float4* fp = (const float4*)(smem + SM_FJ + c * 256);
        unsigned whb_hi = sbase + SM_WHHI + c * 8192;
        unsigned whb_lo = sbase + SM_WHLO + c * 8192;

        // ---- p half0: g = 0..3 (j 0..31) ----
        #pragma unroll
        for (int g = 0; g < 4; g++) {
            float4 a0 = *(const float4*)(arow + (((2 * g)     ^ asw) << 4));
            float4 a1 = *(const float4*)(arow + (((2 * g + 1) ^ asw) << 4));
            float4 f0 = fp[2 * g], f1 = fp[2 * g + 1];
            float p[8];
            float xs[8] = { fiv + f0.x, fiv + f0.y, fiv + f0.z, fiv + f0.w,
                            fiv + f1.x, fiv + f1.y, fiv + f1.z, fiv + f1.w };
            float aa[8] = { a0.x, a0.y, a0.z, a0.w, a1.x, a1.y, a1.z, a1.w };
            #pragma unroll
            for (int e = 0; e < 8; e++) {
                float l = fmaxf(xs[e], ALPHA * xs[e]);
                p[e] = (aa[e] > 0.f) ? __expf(l) : 0.f;
                rowsum += p[e];
            }
            unsigned h0, h1, h2, h3, l0, l1, l2, l3;
            split2(p[0], p[1], h0, l0); split2(p[2], p[3], h1, l1);
            split2(p[4], p[5], h2, l2); split2(p[6], p[7], h3, l3);
            int co = (g ^ asw) << 4;
            *(uint4*)(smem + SM_PHI + tid * 128 + co) = make_uint4(h0, h1, h2, h3);
            *(uint4*)(smem + SM_PLO + tid * 128 + co) = make_uint4(l0, l1, l2, l3);
        }
        __syncthreads();   // p half0 visible

        // prefetch wh(t+1) into the other buffer (not under read conflict)
        if (t + 1 < NT) {
            load_wh_tile(sbase, 1 - c, whhi_g, whlo_g, fj_g, t + 1, tid);
            cpasync_commit();
        }

        // ---- p half1 (g = 4..7) + mma kb 0..1 — independent pipes, interleaved ----
        #pragma unroll
        for (int g = 4; g < 8; g++) {
            float4 a0 = *(const float4*)(arow + (((2 * g)     ^ asw) << 4));
            float4 a1 = *(const float4*)(arow + (((2 * g + 1) ^ asw) << 4));
            float4 f0 = fp[2 * g], f1 = fp[2 * g + 1];
            float p[8];
            float xs[8] = { fiv + f0.x, fiv + f0.y, fiv + f0.z, fiv + f0.w,
                            fiv + f1.x, fiv + f1.y, fiv + f1.z, fiv + f1.w };
            float aa[8] = { a0.x, a0.y, a0.z, a0.w, a1.x, a1.y, a1.z, a1.w };
            #pragma unroll
            for (int e = 0; e < 8; e++) {
                float l = fmaxf(xs[e], ALPHA * xs[e]);
                p[e] = (aa[e] > 0.f) ? __expf(l) : 0.f;
                rowsum += p[e];
            }
            unsigned h0, h1, h2, h3, l0, l1, l2, l3;
            split2(p[0], p[1], h0, l0); split2(p[2], p[3], h1, l1);
            split2(p[4], p[5], h2, l2); split2(p[6], p[7], h3, l3);
            int co = (g ^ asw) << 4;
            *(uint4*)(smem + SM_PHI + tid * 128 + co) = make_uint4(h0, h1, h2, h3);
            *(uint4*)(smem + SM_PLO + tid * 128 + co) = make_uint4(l0, l1, l2, l3);
        }
        #pragma unroll
        for (int kb = 0; kb < 2; kb++) {
            unsigned ah[2][4], al[2][4];
            #pragma unroll
            for (int mb = 0; mb < 2; mb++) {
                int r = 32 * wid + 16 * mb + a_roff;
                int cs = 2 * kb + a_cs;
                unsigned off = (unsigned)(r * 128 + ((cs ^ (r & 7)) << 4));
                ldm_x4(ah[mb], sbase + SM_PHI + off);
                ldm_x4(al[mb], sbase + SM_PLO + off);
            }
            #pragma unroll
            for (int nb2 = 0; nb2 < 4; nb2++) {
                unsigned bh[4], bl[4];
                int rn = nb2 * 16 + b_roff;
                int cs = 2 * kb + b_cs;
                unsigned off = (unsigned)(rn * 128 + ((cs ^ (rn & 7)) << 4));
                ldm_x4(bh, whb_hi + off);
                ldm_x4(bl, whb_lo + off);
                #pragma unroll
                for (int mb = 0; mb < 2; mb++) {
                    mma_bf16(dacc[mb][2 * nb2],     ah[mb], bh[0], bh[1]);
                    mma_bf16(dacc[mb][2 * nb2],     ah[mb], bl[0], bl[1]);
                    mma_bf16(dacc[mb][2 * nb2],     al[mb], bh[0], bh[1]);
                    mma_bf16(dacc[mb][2 * nb2 + 1], ah[mb], bh[2], bh[3]);
                    mma_bf16(dacc[mb][2 * nb2 + 1], ah[mb], bl[2], bl[3]);
                    mma_bf16(dacc[mb][2 * nb2 + 1], al[mb], bh[2], bh[3]);
                }
            }
        }
        __syncthreads();   // p half1 visible; adjbuf fully consumed

        // prefetch adj(t+1): adjbuf free now; overlaps mma kb2..3
        if (t + 1 < NT) {
            load_adj_tile(sbase, adj_r, t + 1, tid);
            cpasync_commit();
        }

        // ---- mma kb 2..3 ----
        #pragma unroll
        for (int kb = 2; kb < 4; kb++) {
            unsigned ah[2][4], al[2][4];
            #pragma unroll
            for (int mb = 0; mb < 2; mb++) {
                int r = 32 * wid + 16 * mb + a_roff;
                int cs = 2 * kb + a_cs;
                unsigned off = (unsigned)(r * 128 + ((cs ^ (r & 7)) << 4));
                ldm_x4(ah[mb], sbase + SM_PHI + off);
                ldm_x4(al[mb], sbase + SM_PLO + off);
            }
            #pragma unroll
            for (int nb2 = 0; nb2 < 4; nb2++) {
                unsigned bh[4], bl[4];
                int rn = nb2 * 16 + b_roff;
                int cs = 2 * kb + b_cs;
                unsigned off = (unsigned)(rn * 128 + ((cs ^ (rn & 7)) << 4));
                ldm_x4(bh, whb_hi + off);
                ldm_x4(bl, whb_lo + off);
                #pragma unroll
                for (int mb = 0; mb < 2; mb++) {
                    mma_bf16(dacc[mb][2 * nb2],     ah[mb], bh[0], bh[1]);
                    mma_bf16(dacc[mb][2 * nb2],     ah[mb], bl[0], bl[1]);
                    mma_bf16(dacc[mb][2 * nb2],     al[mb], bh[0], bh[1]);
                    mma_bf16(dacc[mb][2 * nb2 + 1], ah[mb], bh[2], bh[3]);
                    mma_bf16(dacc[mb][2 * nb2 + 1], ah[mb], bl[2], bl[3]);
                    mma_bf16(dacc[mb][2 * nb2 + 1], al[mb], bh[2], bh[3]);
                }
            }
        }
    }

    // ---- epilogue ----
    size_t rowbase = (size_t)s * BB * NN + (size_t)b * NN + i0;
    rsum[rowbase + tid] = rowsum;
    const int l4 = lane >> 2, lm4 = lane & 3;
    #pragma unroll
    for (int mb = 0; mb < 2; mb++) {
        int r0 = 32 * wid + 16 * mb + l4;
        #pragma unroll
        for (int nb = 0; nb < 8; nb++) {
            int col = 8 * nb + 2 * lm4;
            *(float2*)(part + (rowbase + r0) * FO + col)     = make_float2(dacc[mb][nb][0], dacc[mb][nb][1]);
            *(float2*)(part + (rowbase + r0 + 8) * FO + col) = make_float2(dacc[mb][nb][2], dacc[mb][nb][3]);
        }
    }
}

// ============================================================
// Kernel 3: reduce splits, normalize, relu
// ============================================================
__global__ __launch_bounds__(256)
void gat_reduce_kernel(const float* __restrict__ part,
                       const float* __restrict__ rsum,
                       float* __restrict__ out) {
    int t = blockIdx.x * blockDim.x + threadIdx.x;
    int rowi = t >> 4;
    float rs = 0.f;
    #pragma unroll
    for (int s = 0; s < SPLITS; s++) rs += rsum[(size_t)s * BB * NN + rowi];
    float inv = (rs > 0.f) ? (1.f / rs) : 0.f;
    float4 v = make_float4(0.f, 0.f, 0.f, 0.f);
    #pragma unroll
    for (int s = 0; s < SPLITS; s++) {
        float4 pv = ((const float4*)part)[(size_t)s * BB * NN * 16 + t];
        v.x += pv.x; v.y += pv.y; v.z += pv.z; v.w += pv.w;
    }
    float4 o;
    o.x = fmaxf(v.x * inv, 0.f);
    o.y = fmaxf(v.y * inv, 0.f);
    o.z = fmaxf(v.z * inv, 0.f);
    o.w = fmaxf(v.w * inv, 0.f);
    ((float4*)out)[t] = o;
}

// ============================================================
extern "C" void kernel_launch(void* const* d_in, const int* in_sizes, int n_in,
                              void* d_out, int out_size) {
    const float *h = nullptr, *adj = nullptr, *mask = nullptr, *W = nullptr, *a = nullptr;
    for (int i = 0; i < n_in; i++) {
        switch (in_sizes[i]) {
            case BB * NN * FIN:  h    = (const float*)d_in[i]; break;
            case BB * NN * NN:   adj  = (const float*)d_in[i]; break;
            case BB * NN:        mask = (const float*)d_in[i]; break;
            case FIN * FO:       W    = (const float*)d_in[i]; break;
            case 2 * FO:         a    = (const float*)d_in[i]; break;
        }
    }
    float* out = (float*)d_out;
    float* part; cudaGetSymbolAddress((void**)&part, g_part);
    float* rsum; cudaGetSymbolAddress((void**)&rsum, g_rsum);

    static bool attr_set = false;
    if (!attr_set) {
        cudaFuncSetAttribute(gat_wh_fused,  cudaFuncAttributeMaxDynamicSharedMemorySize, WH_SMEM);
        cudaFuncSetAttribute(gat_attn_hmma, cudaFuncAttributeMaxDynamicSharedMemorySize, SM_TOTAL);
        attr_set = true;
    }

    gat_wh_fused<<<BB * NN / 64, 256, WH_SMEM>>>(h, W, a, mask);
    gat_attn_hmma<<<dim3(NN / TI, BB, SPLITS), 128, SM_TOTAL>>>(adj, part, rsum);
    gat_reduce_kernel<<<BB * NN * 16 / 256, 256>>>(part, rsum, out);
}

// round 14
// speedup vs baseline: 1.6775x; 1.0560x over previous
#include <cuda_runtime.h>
#include <cuda_fp16.h>

#define BB   16
#define NN   2048
#define FIN  128
#define FO   64
#define TI   128
#define TJ   64
#define SPLITS 4
#define NT   (NN / SPLITS / TJ)   // 8
#define ALPHA 0.2f

// attn dynamic smem layout (bytes)
#define SM_PHI  0          // p fp16 [128 x 128B]
#define SM_ADJ  16384      // adj tile [128 rows x 256B], chunk-swizzled
#define SM_WHHI 49152      // wh hi fp16 [2][64 x 128B]
#define SM_WHLO 65536      // wh lo fp16 [2][64 x 128B]
#define SM_FJ   81920      // fj [2][64 floats]
#define SM_TOTAL 82432

#define WH_SMEM (64 * 1024)

// ---- scratch ----
__device__ float    g_fi[BB * NN];
__device__ float    g_fj[BB * NN];
__device__ unsigned g_WhT_hi[BB * FO * (NN / 2)];   // f16x2 [b][o][j/2] (n-major)
__device__ unsigned g_WhT_lo[BB * FO * (NN / 2)];
__device__ float    g_part[SPLITS * BB * NN * FO];
__device__ float    g_rsum[SPLITS * BB * NN];

// ---- f32x2 helpers ----
__device__ __forceinline__ void fma2(unsigned long long& d, unsigned long long a, unsigned long long b) {
    asm("fma.rn.f32x2 %0, %1, %2, %0;" : "+l"(d) : "l"(a), "l"(b));
}
__device__ __forceinline__ unsigned long long pack2(float x, float y) {
    unsigned long long r; asm("mov.b64 %0, {%1, %2};" : "=l"(r) : "f"(x), "f"(y)); return r;
}
__device__ __forceinline__ float2 unpack2(unsigned long long v) {
    float2 r; asm("mov.b64 {%0, %1}, %2;" : "=f"(r.x), "=f"(r.y) : "l"(v)); return r;
}

// ---- cp.async ----
__device__ __forceinline__ void cpasync16(unsigned s, const void* g) {
    asm volatile("cp.async.cg.shared.global [%0], [%1], 16;" :: "r"(s), "l"(g) : "memory");
}
__device__ __forceinline__ void cpasync_commit() { asm volatile("cp.async.commit_group;" ::: "memory"); }
__device__ __forceinline__ void cpasync_wait_all() {
    asm volatile("cp.async.wait_group 0;" ::: "memory");
}

// ---- tensor-core (base ISA) ----
__device__ __forceinline__ void ldm_x4(unsigned* d, unsigned saddr) {
    asm volatile("ldmatrix.sync.aligned.m8n8.x4.shared.b16 {%0,%1,%2,%3}, [%4];"
                 : "=r"(d[0]), "=r"(d[1]), "=r"(d[2]), "=r"(d[3]) : "r"(saddr));
}
__device__ __forceinline__ void mma_f16(float* d, const unsigned* a, unsigned b0, unsigned b1) {
    asm volatile("mma.sync.aligned.m16n8k16.row.col.f32.f16.f16.f32 "
                 "{%0,%1,%2,%3}, {%4,%5,%6,%7}, {%8,%9}, {%0,%1,%2,%3};"
                 : "+f"(d[0]), "+f"(d[1]), "+f"(d[2]), "+f"(d[3])
                 : "r"(a[0]), "r"(a[1]), "r"(a[2]), "r"(a[3]), "r"(b0), "r"(b1));
}

// pack two fp32 -> f16x2 {lo16 = v0, hi16 = v1}
__device__ __forceinline__ unsigned pack_f16x2(float v0, float v1) {
    unsigned r; asm("cvt.rn.f16x2.f32 %0, %1, %2;" : "=r"(r) : "f"(v1), "f"(v0)); return r;
}
// fp16 hi/lo split of two fp32 values (w exact to ~2^-21)
__device__ __forceinline__ void split2h(float v0, float v1, unsigned& hi, unsigned& lo) {
    hi = pack_f16x2(v0, v1);
    float h0 = __half2float(__ushort_as_half((unsigned short)(hi & 0xFFFF)));
    float h1 = __half2float(__ushort_as_half((unsigned short)(hi >> 16)));
    lo = pack_f16x2(v0 - h0, v1 - h1);
}

// ============================================================
// Kernel 1 (fused): Wh = h @ W, masked f_i/f_j, and WhT fp16
// hi/lo split-transpose — all in one pass. 64 rows/block.
// ============================================================
__global__ __launch_bounds__(256)
void gat_wh_fused(const float* __restrict__ h, const float* __restrict__ W,
                  const float* __restrict__ a, const float* __restrict__ mask) {
    extern __shared__ float ws[];
    float* h_s = ws;              // 64*128 floats (32KB)
    float* W_s = ws + 64 * FIN;   // 128*64 floats (32KB)

    int tid = threadIdx.x;
    size_t base = (size_t)blockIdx.x * 64;

    {
        const float4* hsrc = (const float4*)(h + base * FIN);
        float4* hdst = (float4*)h_s;
        #pragma unroll
        for (int r = 0; r < 8; r++) hdst[r * 256 + tid] = hsrc[r * 256 + tid];
        const float4* wsrc = (const float4*)W;
        float4* wdst = (float4*)W_s;
        #pragma unroll
        for (int r = 0; r < 8; r++) wdst[r * 256 + tid] = wsrc[r * 256 + tid];
    }
    __syncthreads();

    int r = tid >> 4, og = tid & 15;
    unsigned long long acc[8];    // 4 rows x 4 floats
    #pragma unroll
    for (int z = 0; z < 8; z++) acc[z] = 0ull;

    #pragma unroll 2
    for (int k = 0; k < FIN; k += 4) {
        float4 hv[4];
        #pragma unroll
        for (int q = 0; q < 4; q++)
            hv[q] = *(const float4*)(h_s + (r + 16 * q) * FIN + k);
        #pragma unroll
        for (int t = 0; t < 4; t++) {
            ulonglong2 w = *(const ulonglong2*)(W_s + (k + t) * FO + og * 4);
            #pragma unroll
            for (int q = 0; q < 4; q++) {
                float v = (t == 0) ? hv[q].x : (t == 1) ? hv[q].y : (t == 2) ? hv[q].z : hv[q].w;
                unsigned long long v2 = pack2(v, v);
                fma2(acc[2 * q],     v2, w.x);
                fma2(acc[2 * q + 1], v2, w.y);
            }
        }
    }

    int o = og * 4;
    float a_s0 = a[o],      a_s1 = a[o + 1],      a_s2 = a[o + 2],      a_s3 = a[o + 3];
    float a_d0 = a[FO + o], a_d1 = a[FO + o + 1], a_d2 = a[FO + o + 2], a_d3 = a[FO + o + 3];
    __syncthreads();          // done reading h_s; reuse as wt[64][65]
    float* wt = h_s;
    #pragma unroll
    for (int q = 0; q < 4; q++) {
        float2 p01 = unpack2(acc[2 * q]);
        float2 p23 = unpack2(acc[2 * q + 1]);
        int rowl = r + 16 * q;
        wt[rowl * 65 + o]     = p01.x;
        wt[rowl * 65 + o + 1] = p01.y;
        wt[rowl * 65 + o + 2] = p23.x;
        wt[rowl * 65 + o + 3] = p23.y;

        float ps = p01.x * a_s0 + p01.y * a_s1 + p23.x * a_s2 + p23.y * a_s3;
        float pd = p01.x * a_d0 + p01.y * a_d1 + p23.x * a_d2 + p23.y * a_d3;
        #pragma unroll
        for (int off = 8; off >= 1; off >>= 1) {
            ps += __shfl_down_sync(0xffffffffu, ps, off, 16);
            pd += __shfl_down_sync(0xffffffffu, pd, off, 16);
        }
        if (og == 0) {
            size_t row = base + rowl;
            bool ok = mask[row] > 0.f;
            g_fi[row] = ok ? ps : -1e30f;
            g_fj[row] = ok ? pd : -1e30f;
        }
    }
    __syncthreads();

    // split-transpose (fp16 hi/lo): thread (oo = tid>>2, q = tid&3), 8 j-pairs
    {
        int oo = tid >> 2, q = tid & 3;
        unsigned oh[8], ol[8];
        #pragma unroll
        for (int u = 0; u < 8; u++) {
            int j = 16 * q + 2 * u;
            split2h(wt[j * 65 + oo], wt[(j + 1) * 65 + oo], oh[u], ol[u]);
        }
        int bb = (int)(base >> 11);
        int n0 = (int)(base & (NN - 1));
        size_t ob = (size_t)bb * FO * (NN / 2) + (size_t)oo * (NN / 2) + n0 / 2 + q * 8;
        *(uint4*)(g_WhT_hi + ob)     = make_uint4(oh[0], oh[1], oh[2], oh[3]);
        *(uint4*)(g_WhT_hi + ob + 4) = make_uint4(oh[4], oh[5], oh[6], oh[7]);
        *(uint4*)(g_WhT_lo + ob)     = make_uint4(ol[0], ol[1], ol[2], ol[3]);
        *(uint4*)(g_WhT_lo + ob + 4) = make_uint4(ol[4], ol[5], ol[6], ol[7]);
    }
}

// ============================================================
// Kernel 2: attention (champion structure, fp16 2-term datapath).
// 128 threads / 4 warps; warp w owns rows 32w..32w+31, N=64.
// D = ph * (wh + wl): p single fp16, w fp16-split (exact).
// ============================================================
__device__ __forceinline__ void load_wh_tile(unsigned sbase, int buf, const unsigned* hi_g,
                                             const unsigned* lo_g, const float* fj_g,
                                             int jt, int tid) {
    #pragma unroll
    for (int k = 0; k < 4; k++) {
        int idx = tid + k * 128;              // 0..511
        int o = idx >> 3, cc = idx & 7;
        unsigned co = (unsigned)((cc ^ (o & 7)) * 16);
        cpasync16(sbase + SM_WHHI + buf * 8192 + o * 128 + co,
                  hi_g + (size_t)o * (NN / 2) + jt * 32 + cc * 4);
        cpasync16(sbase + SM_WHLO + buf * 8192 + o * 128 + co,
                  lo_g + (size_t)o * (NN / 2) + jt * 32 + cc * 4);
    }
    if (tid < 16)
        cpasync16(sbase + SM_FJ + buf * 256 + tid * 16, fj_g + jt * TJ + tid * 4);
}

__device__ __forceinline__ void load_adj_tile(unsigned sbase, const float* adj_row, int t, int tid) {
    unsigned dstrow = sbase + SM_ADJ + (unsigned)tid * 256;
    const float* src = adj_row + t * TJ;
    #pragma unroll
    for (int cchunk = 0; cchunk < 16; cchunk++)
        cpasync16(dstrow + ((unsigned)(cchunk ^ (tid & 7)) << 4), src + cchunk * 4);
}

__global__ __launch_bounds__(128)
void gat_attn_hmma(const float* __restrict__ adj,
                   float* __restrict__ part, float* __restrict__ rsum) {
    extern __shared__ char smem[];
    unsigned sbase = (unsigned)__cvta_generic_to_shared(smem);
    const int tid = threadIdx.x;
    const int wid = tid >> 5, lane = tid & 31;
    const int b = blockIdx.y, s = blockIdx.z;
    const int i0 = blockIdx.x * TI;
    const int jbeg = s * (NN / SPLITS);

    const float* adj_r = adj + (size_t)b * NN * NN + (size_t)(i0 + tid) * NN + jbeg;
    const float* fj_g  = g_fj + b * NN + jbeg;
    const float  fiv   = g_fi[b * NN + i0 + tid];
    const unsigned* whhi_g = g_WhT_hi + (size_t)b * FO * (NN / 2) + jbeg / 2;
    const unsigned* whlo_g = g_WhT_lo + (size_t)b * FO * (NN / 2) + jbeg / 2;

    float dacc[2][8][4];
    #pragma unroll
    for (int mb = 0; mb < 2; mb++)
        #pragma unroll
        for (int nb = 0; nb < 8; nb++)
            #pragma unroll
            for (int z = 0; z < 4; z++) dacc[mb][nb][z] = 0.f;
    float rowsum = 0.f;

    // prologue: adj(0) + wh(0) + fj(0)
    load_adj_tile(sbase, adj_r, 0, tid);
    load_wh_tile(sbase, 0, whhi_g, whlo_g, fj_g, 0, tid);
    cpasync_commit();

    const int a_roff = ((lane >> 3) & 1) * 8 + (lane & 7);
    const int a_cs   = lane >> 4;
    const int b_roff = ((lane >> 4) << 3) + (lane & 7);
    const int b_cs   = (lane >> 3) & 1;
    const int asw    = tid & 7;
    const char* arow = smem + SM_ADJ + tid * 256;

    for (int t = 0; t < NT; t++) {
        int c = t & 1;

        cpasync_wait_all();
        __syncthreads();   // adj(t)/wh(t)/fj(t) visible; p(t-1) fully consumed

        const float4* fp = (const float4*)(smem + SM_FJ + c * 256);
        unsigned whb_hi = sbase + SM_WHHI + c * 8192;
        unsigned whb_lo = sbase + SM_WHLO + c * 8192;

        // ---- p half0: g = 0..3 (j 0..31) ----
        #pragma unroll
        for (int g = 0; g < 4; g++) {
            float4 a0 = *(const float4*)(arow + (((2 * g)     ^ asw) << 4));
            float4 a1 = *(const float4*)(arow + (((2 * g + 1) ^ asw) << 4));
            float4 f0 = fp[2 * g], f1 = fp[2 * g + 1];
            float p[8];
            float xs[8] = { fiv + f0.x, fiv + f0.y, fiv + f0.z, fiv + f0.w,
                            fiv + f1.x, fiv + f1.y, fiv + f1.z, fiv + f1.w };
            float aa[8] = { a0.x, a0.y, a0.z, a0.w, a1.x, a1.y, a1.z, a1.w };
            #pragma unroll
            for (int e = 0; e < 8; e++) {
                float l = fmaxf(xs[e], ALPHA * xs[e]);
                p[e] = (aa[e] > 0.f) ? __expf(l) : 0.f;
                rowsum += p[e];
            }
            uint4 ph = make_uint4(pack_f16x2(p[0], p[1]), pack_f16x2(p[2], p[3]),
                                  pack_f16x2(p[4], p[5]), pack_f16x2(p[6], p[7]));
            *(uint4*)(smem + SM_PHI + tid * 128 + ((g ^ asw) << 4)) = ph;
        }
        __syncthreads();   // p half0 visible

        // prefetch wh(t+1)
        if (t + 1 < NT) {
            load_wh_tile(sbase, 1 - c, whhi_g, whlo_g, fj_g, t + 1, tid);
            cpasync_commit();
        }

        // ---- p half1 (g = 4..7) + mma kb 0..1 — independent pipes ----
        #pragma unroll
        for (int g = 4; g < 8; g++) {
            float4 a0 = *(const float4*)(arow + (((2 * g)     ^ asw) << 4));
            float4 a1 = *(const float4*)(arow + (((2 * g + 1) ^ asw) << 4));
            float4 f0 = fp[2 * g], f1 = fp[2 * g + 1];
            float p[8];
            float xs[8] = { fiv + f0.x, fiv + f0.y, fiv + f0.z, fiv + f0.w,
                            fiv + f1.x, fiv + f1.y, fiv + f1.z, fiv + f1.w };
            float aa[8] = { a0.x, a0.y, a0.z, a0.w, a1.x, a1.y, a1.z, a1.w };
            #pragma unroll
            for (int e = 0; e < 8; e++) {
                float l = fmaxf(xs[e], ALPHA * xs[e]);
                p[e] = (aa[e] > 0.f) ? __expf(l) : 0.f;
                rowsum += p[e];
            }
            uint4 ph = make_uint4(pack_f16x2(p[0], p[1]), pack_f16x2(p[2], p[3]),
                                  pack_f16x2(p[4], p[5]), pack_f16x2(p[6], p[7]));
            *(uint4*)(smem + SM_PHI + tid * 128 + ((g ^ asw) << 4)) = ph;
        }
        #pragma unroll
        for (int kb = 0; kb < 2; kb++) {
            unsigned ah[2][4];
            #pragma unroll
            for (int mb = 0; mb < 2; mb++) {
                int r = 32 * wid + 16 * mb + a_roff;
                int cs = 2 * kb + a_cs;
                ldm_x4(ah[mb], sbase + SM_PHI + (unsigned)(r * 128 + ((cs ^ (r & 7)) << 4)));
            }
            #pragma unroll
            for (int nb2 = 0; nb2 < 4; nb2++) {
                unsigned bh[4], bl[4];
                int rn = nb2 * 16 + b_roff;
                int cs = 2 * kb + b_cs;
                unsigned off = (unsigned)(rn * 128 + ((cs ^ (rn & 7)) << 4));
                ldm_x4(bh, whb_hi + off);
                ldm_x4(bl, whb_lo + off);
                #pragma unroll
                for (int mb = 0; mb < 2; mb++) {
                    mma_f16(dacc[mb][2 * nb2],     ah[mb], bh[0], bh[1]);
                    mma_f16(dacc[mb][2 * nb2],     ah[mb], bl[0], bl[1]);
                    mma_f16(dacc[mb][2 * nb2 + 1], ah[mb], bh[2], bh[3]);
                    mma_f16(dacc[mb][2 * nb2 + 1], ah[mb], bl[2], bl[3]);
                }
            }
        }
        __syncthreads();   // p half1 visible; adjbuf fully consumed

        // prefetch adj(t+1): overlaps mma kb2..3
        if (t + 1 < NT) {
            load_adj_tile(sbase, adj_r, t + 1, tid);
            cpasync_commit();
        }

        // ---- mma kb 2..3 ----
        #pragma unroll
        for (int kb = 2; kb < 4; kb++) {
            unsigned ah[2][4];
            #pragma unroll
            for (int mb = 0; mb < 2; mb++) {
                int r = 32 * wid + 16 * mb + a_roff;
                int cs = 2 * kb + a_cs;
                ldm_x4(ah[mb], sbase + SM_PHI + (unsigned)(r * 128 + ((cs ^ (r & 7)) << 4)));
            }
            #pragma unroll
            for (int nb2 = 0; nb2 < 4; nb2++) {
                unsigned bh[4], bl[4];
                int rn = nb2 * 16 + b_roff;
                int cs = 2 * kb + b_cs;
                unsigned off = (unsigned)(rn * 128 + ((cs ^ (rn & 7)) << 4));
                ldm_x4(bh, whb_hi + off);
                ldm_x4(bl, whb_lo + off);
                #pragma unroll
                for (int mb = 0; mb < 2; mb++) {
                    mma_f16(dacc[mb][2 * nb2],     ah[mb], bh[0], bh[1]);
                    mma_f16(dacc[mb][2 * nb2],     ah[mb], bl[0], bl[1]);
                    mma_f16(dacc[mb][2 * nb2 + 1], ah[mb], bh[2], bh[3]);
                    mma_f16(dacc[mb][2 * nb2 + 1], ah[mb], bl[2], bl[3]);
                }
            }
        }
    }

    // ---- epilogue ----
    size_t rowbase = (size_t)s * BB * NN + (size_t)b * NN + i0;
    rsum[rowbase + tid] = rowsum;
    const int l4 = lane >> 2, lm4 = lane & 3;
    #pragma unroll
    for (int mb = 0; mb < 2; mb++) {
        int r0 = 32 * wid + 16 * mb + l4;
        #pragma unroll
        for (int nb = 0; nb < 8; nb++) {
            int col = 8 * nb + 2 * lm4;
            *(float2*)(part + (rowbase + r0) * FO + col)     = make_float2(dacc[mb][nb][0], dacc[mb][nb][1]);
            *(float2*)(part + (rowbase + r0 + 8) * FO + col) = make_float2(dacc[mb][nb][2], dacc[mb][nb][3]);
        }
    }
}

// ============================================================
// Kernel 3: reduce splits, normalize, relu
// ============================================================
__global__ __launch_bounds__(256)
void gat_reduce_kernel(const float* __restrict__ part,
                       const float* __restrict__ rsum,
                       float* __restrict__ out) {
    int t = blockIdx.x * blockDim.x + threadIdx.x;
    int rowi = t >> 4;
    float rs = 0.f;
    #pragma unroll
    for (int s = 0; s < SPLITS; s++) rs += rsum[(size_t)s * BB * NN + rowi];
    float inv = (rs > 0.f) ? (1.f / rs) : 0.f;
    float4 v = make_float4(0.f, 0.f, 0.f, 0.f);
    #pragma unroll
    for (int s = 0; s < SPLITS; s++) {
        float4 pv = ((const float4*)part)[(size_t)s * BB * NN * 16 + t];
        v.x += pv.x; v.y += pv.y; v.z += pv.z; v.w += pv.w;
    }
    float4 o;
    o.x = fmaxf(v.x * inv, 0.f);
    o.y = fmaxf(v.y * inv, 0.f);
    o.z = fmaxf(v.z * inv, 0.f);
    o.w = fmaxf(v.w * inv, 0.f);
    ((float4*)out)[t] = o;
}

// ============================================================
extern "C" void kernel_launch(void* const* d_in, const int* in_sizes, int n_in,
                              void* d_out, int out_size) {
    const float *h = nullptr, *adj = nullptr, *mask = nullptr, *W = nullptr, *a = nullptr;
    for (int i = 0; i < n_in; i++) {
        switch (in_sizes[i]) {
            case BB * NN * FIN:  h    = (const float*)d_in[i]; break;
            case BB * NN * NN:   adj  = (const float*)d_in[i]; break;
            case BB * NN:        mask = (const float*)d_in[i]; break;
            case FIN * FO:       W    = (const float*)d_in[i]; break;
            case 2 * FO:         a    = (const float*)d_in[i]; break;
        }
    }
    float* out = (float*)d_out;
    float* part; cudaGetSymbolAddress((void**)&part, g_part);
    float* rsum; cudaGetSymbolAddress((void**)&rsum, g_rsum);

    static bool attr_set = false;
    if (!attr_set) {
        cudaFuncSetAttribute(gat_wh_fused,  cudaFuncAttributeMaxDynamicSharedMemorySize, WH_SMEM);
        cudaFuncSetAttribute(gat_attn_hmma, cudaFuncAttributeMaxDynamicSharedMemorySize, SM_TOTAL);
        attr_set = true;
    }

    gat_wh_fused<<<BB * NN / 64, 256, WH_SMEM>>>(h, W, a, mask);
    gat_attn_hmma<<<dim3(NN / TI, BB, SPLITS), 128, SM_TOTAL>>>(adj, part, rsum);
    gat_reduce_kernel<<<BB * NN * 16 / 256, 256>>>(part, rsum, out);
}

// round 16
// speedup vs baseline: 1.9219x; 1.1457x over previous
#include <cuda_runtime.h>
#include <cuda_fp16.h>

#define BB   16
#define NN   2048
#define FIN  128
#define FO   64
#define TI   128
#define TJ   64
#define SPLITS 4
#define NT   (NN / SPLITS / TJ)   // 8
#define ALPHA 0.2f

// attn dynamic smem layout (bytes)
#define SM_PHI  0          // p fp16 [128 x 128B]
#define SM_ADJ  16384      // adj tile [128 rows x 256B], chunk-swizzled
#define SM_WHHI 49152      // wh fp16 [2][64 x 128B]
#define SM_FJ   65536      // fj [2][64 floats]
#define SM_TOTAL 66048

#define WH_SMEM (64 * 1024)

// ---- scratch ----
__device__ float    g_fi[BB * NN];
__device__ float    g_fj[BB * NN];
__device__ unsigned g_WhT_hi[BB * FO * (NN / 2)];   // f16x2 [b][o][j/2] (n-major)
__device__ float    g_part[SPLITS * BB * NN * FO];
__device__ float    g_rsum[SPLITS * BB * NN];

// ---- f32x2 helpers ----
__device__ __forceinline__ void fma2(unsigned long long& d, unsigned long long a, unsigned long long b) {
    asm("fma.rn.f32x2 %0, %1, %2, %0;" : "+l"(d) : "l"(a), "l"(b));
}
__device__ __forceinline__ unsigned long long pack2(float x, float y) {
    unsigned long long r; asm("mov.b64 %0, {%1, %2};" : "=l"(r) : "f"(x), "f"(y)); return r;
}
__device__ __forceinline__ float2 unpack2(unsigned long long v) {
    float2 r; asm("mov.b64 {%0, %1}, %2;" : "=f"(r.x), "=f"(r.y) : "l"(v)); return r;
}

// ---- cp.async ----
__device__ __forceinline__ void cpasync16(unsigned s, const void* g) {
    asm volatile("cp.async.cg.shared.global [%0], [%1], 16;" :: "r"(s), "l"(g) : "memory");
}
__device__ __forceinline__ void cpasync_commit() { asm volatile("cp.async.commit_group;" ::: "memory"); }
__device__ __forceinline__ void cpasync_wait_all() {
    asm volatile("cp.async.wait_group 0;" ::: "memory");
}

// ---- tensor-core (base ISA) ----
__device__ __forceinline__ void ldm_x4(unsigned* d, unsigned saddr) {
    asm volatile("ldmatrix.sync.aligned.m8n8.x4.shared.b16 {%0,%1,%2,%3}, [%4];"
                 : "=r"(d[0]), "=r"(d[1]), "=r"(d[2]), "=r"(d[3]) : "r"(saddr));
}
__device__ __forceinline__ void mma_f16(float* d, const unsigned* a, unsigned b0, unsigned b1) {
    asm volatile("mma.sync.aligned.m16n8k16.row.col.f32.f16.f16.f32 "
                 "{%0,%1,%2,%3}, {%4,%5,%6,%7}, {%8,%9}, {%0,%1,%2,%3};"
                 : "+f"(d[0]), "+f"(d[1]), "+f"(d[2]), "+f"(d[3])
                 : "r"(a[0]), "r"(a[1]), "r"(a[2]), "r"(a[3]), "r"(b0), "r"(b1));
}

// pack two fp32 -> f16x2 {lo16 = v0, hi16 = v1}
__device__ __forceinline__ unsigned pack_f16x2(float v0, float v1) {
    unsigned r; asm("cvt.rn.f16x2.f32 %0, %1, %2;" : "=r"(r) : "f"(v1), "f"(v0)); return r;
}

// ============================================================
// Kernel 1 (fused): Wh = h @ W, masked f_i/f_j, and WhT fp16
// transpose — all in one pass. 64 rows/block.
// ============================================================
__global__ __launch_bounds__(256)
void gat_wh_fused(const float* __restrict__ h, const float* __restrict__ W,
                  const float* __restrict__ a, const float* __restrict__ mask) {
    extern __shared__ float ws[];
    float* h_s = ws;              // 64*128 floats (32KB)
    float* W_s = ws + 64 * FIN;   // 128*64 floats (32KB)

    int tid = threadIdx.x;
    size_t base = (size_t)blockIdx.x * 64;

    {
        const float4* hsrc = (const float4*)(h + base * FIN);
        float4* hdst = (float4*)h_s;
        #pragma unroll
        for (int r = 0; r < 8; r++) hdst[r * 256 + tid] = hsrc[r * 256 + tid];
        const float4* wsrc = (const float4*)W;
        float4* wdst = (float4*)W_s;
        #pragma unroll
        for (int r = 0; r < 8; r++) wdst[r * 256 + tid] = wsrc[r * 256 + tid];
    }
    __syncthreads();

    int r = tid >> 4, og = tid & 15;
    unsigned long long acc[8];    // 4 rows x 4 floats
    #pragma unroll
    for (int z = 0; z < 8; z++) acc[z] = 0ull;

    #pragma unroll 2
    for (int k = 0; k < FIN; k += 4) {
        float4 hv[4];
        #pragma unroll
        for (int q = 0; q < 4; q++)
            hv[q] = *(const float4*)(h_s + (r + 16 * q) * FIN + k);
        #pragma unroll
        for (int t = 0; t < 4; t++) {
            ulonglong2 w = *(const ulonglong2*)(W_s + (k + t) * FO + og * 4);
            #pragma unroll
            for (int q = 0; q < 4; q++) {
                float v = (t == 0) ? hv[q].x : (t == 1) ? hv[q].y : (t == 2) ? hv[q].z : hv[q].w;
                unsigned long long v2 = pack2(v, v);
                fma2(acc[2 * q],     v2, w.x);
                fma2(acc[2 * q + 1], v2, w.y);
            }
        }
    }

    int o = og * 4;
    float a_s0 = a[o],      a_s1 = a[o + 1],      a_s2 = a[o + 2],      a_s3 = a[o + 3];
    float a_d0 = a[FO + o], a_d1 = a[FO + o + 1], a_d2 = a[FO + o + 2], a_d3 = a[FO + o + 3];
    __syncthreads();          // done reading h_s; reuse as wt[64][65]
    float* wt = h_s;
    #pragma unroll
    for (int q = 0; q < 4; q++) {
        float2 p01 = unpack2(acc[2 * q]);
        float2 p23 = unpack2(acc[2 * q + 1]);
        int rowl = r + 16 * q;
        wt[rowl * 65 + o]     = p01.x;
        wt[rowl * 65 + o + 1] = p01.y;
        wt[rowl * 65 + o + 2] = p23.x;
        wt[rowl * 65 + o + 3] = p23.y;

        float ps = p01.x * a_s0 + p01.y * a_s1 + p23.x * a_s2 + p23.y * a_s3;
        float pd = p01.x * a_d0 + p01.y * a_d1 + p23.x * a_d2 + p23.y * a_d3;
        #pragma unroll
        for (int off = 8; off >= 1; off >>= 1) {
            ps += __shfl_down_sync(0xffffffffu, ps, off, 16);
            pd += __shfl_down_sync(0xffffffffu, pd, off, 16);
        }
        if (og == 0) {
            size_t row = base + rowl;
            bool ok = mask[row] > 0.f;
            g_fi[row] = ok ? ps : -1e30f;
            g_fj[row] = ok ? pd : -1e30f;
        }
    }
    __syncthreads();

    // fp16 transpose: thread (oo = tid>>2, q = tid&3), 8 j-pairs
    {
        int oo = tid >> 2, q = tid & 3;
        unsigned oh[8];
        #pragma unroll
        for (int u = 0; u < 8; u++) {
            int j = 16 * q + 2 * u;
            oh[u] = pack_f16x2(wt[j * 65 + oo], wt[(j + 1) * 65 + oo]);
        }
        int bb = (int)(base >> 11);
        int n0 = (int)(base & (NN - 1));
        size_t ob = (size_t)bb * FO * (NN / 2) + (size_t)oo * (NN / 2) + n0 / 2 + q * 8;
        *(uint4*)(g_WhT_hi + ob)     = make_uint4(oh[0], oh[1], oh[2], oh[3]);
        *(uint4*)(g_WhT_hi + ob + 4) = make_uint4(oh[4], oh[5], oh[6], oh[7]);
    }
}

// ============================================================
// Kernel 2: attention (champion structure, single fp16 mma).
// 128 threads / 4 warps; warp w owns rows 32w..32w+31, N=64.
// 64.5 KB smem -> 3 blocks/SM for cross-block phase overlap.
// ============================================================
__device__ __forceinline__ void load_wh_tile(unsigned sbase, int buf, const unsigned* hi_g,
                                             const float* fj_g, int jt, int tid) {
    #pragma unroll
    for (int k = 0; k < 4; k++) {
        int idx = tid + k * 128;              // 0..511
        int o = idx >> 3, cc = idx & 7;
        unsigned co = (unsigned)((cc ^ (o & 7)) * 16);
        cpasync16(sbase + SM_WHHI + buf * 8192 + o * 128 + co,
                  hi_g + (size_t)o * (NN / 2) + jt * 32 + cc * 4);
    }
    if (tid < 16)
        cpasync16(sbase + SM_FJ + buf * 256 + tid * 16, fj_g + jt * TJ + tid * 4);
}

__device__ __forceinline__ void load_adj_tile(unsigned sbase, const float* adj_row, int t, int tid) {
    unsigned dstrow = sbase + SM_ADJ + (unsigned)tid * 256;
    const float* src = adj_row + t * TJ;
    #pragma unroll
    for (int cchunk = 0; cchunk < 16; cchunk++)
        cpasync16(dstrow + ((unsigned)(cchunk ^ (tid & 7)) << 4), src + cchunk * 4);
}

__global__ __launch_bounds__(128)
void gat_attn_hmma(const float* __restrict__ adj,
                   float* __restrict__ part, float* __restrict__ rsum) {
    extern __shared__ char smem[];
    unsigned sbase = (unsigned)__cvta_generic_to_shared(smem);
    const int tid = threadIdx.x;
    const int wid = tid >> 5, lane = tid & 31;
    const int b = blockIdx.y, s = blockIdx.z;
    const int i0 = blockIdx.x * TI;
    const int jbeg = s * (NN / SPLITS);

    const float* adj_r = adj + (size_t)b * NN * NN + (size_t)(i0 + tid) * NN + jbeg;
    const float* fj_g  = g_fj + b * NN + jbeg;
    const float  fiv   = g_fi[b * NN + i0 + tid];
    const unsigned* whhi_g = g_WhT_hi + (size_t)b * FO * (NN / 2) + jbeg / 2;

    float dacc[2][8][4];
    #pragma unroll
    for (int mb = 0; mb < 2; mb++)
        #pragma unroll
        for (int nb = 0; nb < 8; nb++)
            #pragma unroll
            for (int z = 0; z < 4; z++) dacc[mb][nb][z] = 0.f;
    float rowsum = 0.f;

    // prologue: adj(0) + wh(0) + fj(0)
    load_adj_tile(sbase, adj_r, 0, tid);
    load_wh_tile(sbase, 0, whhi_g, fj_g, 0, tid);
    cpasync_commit();

    const int a_roff = ((lane >> 3) & 1) * 8 + (lane & 7);
    const int a_cs   = lane >> 4;
    const int b_roff = ((lane >> 4) << 3) + (lane & 7);
    const int b_cs   = (lane >> 3) & 1;
    const int asw    = tid & 7;
    const char* arow = smem + SM_ADJ + tid * 256;

    for (int t = 0; t < NT; t++) {
        int c = t & 1;

        cpasync_wait_all();
        __syncthreads();   // adj(t)/wh(t)/fj(t) visible; p(t-1) fully consumed

        const float4* fp = (const float4*)(smem + SM_FJ + c * 256);
        unsigned whb_hi = sbase + SM_WHHI + c * 8192;

        // ---- p half0: g = 0..3 (j 0..31) ----
        #pragma unroll
        for (int g = 0; g < 4; g++) {
            float4 a0 = *(const float4*)(arow + (((2 * g)     ^ asw) << 4));
            float4 a1 = *(const float4*)(arow + (((2 * g + 1) ^ asw) << 4));
            float4 f0 = fp[2 * g], f1 = fp[2 * g + 1];
            float p[8];
            float xs[8] = { fiv + f0.x, fiv + f0.y, fiv + f0.z, fiv + f0.w,
                            fiv + f1.x, fiv + f1.y, fiv + f1.z, fiv + f1.w };
            float aa[8] = { a0.x, a0.y, a0.z, a0.w, a1.x, a1.y, a1.z, a1.w };
            #pragma unroll
            for (int e = 0; e < 8; e++) {
                float l = fmaxf(xs[e], ALPHA * xs[e]);
                p[e] = (aa[e] > 0.f) ? __expf(l) : 0.f;
                rowsum += p[e];
            }
            uint4 ph = make_uint4(pack_f16x2(p[0], p[1]), pack_f16x2(p[2], p[3]),
                                  pack_f16x2(p[4], p[5]), pack_f16x2(p[6], p[7]));
            *(uint4*)(smem + SM_PHI + tid * 128 + ((g ^ asw) << 4)) = ph;
        }
        __syncthreads();   // p half0 visible

        // prefetch wh(t+1)
        if (t + 1 < NT) {
            load_wh_tile(sbase, 1 - c, whhi_g, fj_g, t + 1, tid);
            cpasync_commit();
        }

        // ---- p half1 (g = 4..7) + mma kb 0..1 — independent pipes ----
        #pragma unroll
        for (int g = 4; g < 8; g++) {
            float4 a0 = *(const float4*)(arow + (((2 * g)     ^ asw) << 4));
            float4 a1 = *(const float4*)(arow + (((2 * g + 1) ^ asw) << 4));
            float4 f0 = fp[2 * g], f1 = fp[2 * g + 1];
            float p[8];
            float xs[8] = { fiv + f0.x, fiv + f0.y, fiv + f0.z, fiv + f0.w,
                            fiv + f1.x, fiv + f1.y, fiv + f1.z, fiv + f1.w };
            float aa[8] = { a0.x, a0.y, a0.z, a0.w, a1.x, a1.y, a1.z, a1.w };
            #pragma unroll
            for (int e = 0; e < 8; e++) {
                float l = fmaxf(xs[e], ALPHA * xs[e]);
                p[e] = (aa[e] > 0.f) ? __expf(l) : 0.f;
                rowsum += p[e];
            }
            uint4 ph = make_uint4(pack_f16x2(p[0], p[1]), pack_f16x2(p[2], p[3]),
                                  pack_f16x2(p[4], p[5]), pack_f16x2(p[6], p[7]));
            *(uint4*)(smem + SM_PHI + tid * 128 + ((g ^ asw) << 4)) = ph;
        }
        #pragma unroll
        for (int kb = 0; kb < 2; kb++) {
            unsigned ah[2][4];
            #pragma unroll
            for (int mb = 0; mb < 2; mb++) {
                int r = 32 * wid + 16 * mb + a_roff;
                int cs = 2 * kb + a_cs;
                ldm_x4(ah[mb], sbase + SM_PHI + (unsigned)(r * 128 + ((cs ^ (r & 7)) << 4)));
            }
            #pragma unroll
            for (int nb2 = 0; nb2 < 4; nb2++) {
                unsigned bh[4];
                int rn = nb2 * 16 + b_roff;
                int cs = 2 * kb + b_cs;
                ldm_x4(bh, whb_hi + (unsigned)(rn * 128 + ((cs ^ (rn & 7)) << 4)));
                #pragma unroll
                for (int mb = 0; mb < 2; mb++) {
                    mma_f16(dacc[mb][2 * nb2],     ah[mb], bh[0], bh[1]);
                    mma_f16(dacc[mb][2 * nb2 + 1], ah[mb], bh[2], bh[3]);
                }
            }
        }
        __syncthreads();   // p half1 visible; adjbuf fully consumed

        // prefetch adj(t+1): overlaps mma kb2..3
        if (t + 1 < NT) {
            load_adj_tile(sbase, adj_r, t + 1, tid);
            cpasync_commit();
        }

        // ---- mma kb 2..3 ----
        #pragma unroll
        for (int kb = 2; kb < 4; kb++) {
            unsigned ah[2][4];
            #pragma unroll
            for (int mb = 0; mb < 2; mb++) {
                int r = 32 * wid + 16 * mb + a_roff;
                int cs = 2 * kb + a_cs;
                ldm_x4(ah[mb], sbase + SM_PHI + (unsigned)(r * 128 + ((cs ^ (r & 7)) << 4)));
            }
            #pragma unroll
            for (int nb2 = 0; nb2 < 4; nb2++) {
                unsigned bh[4];
                int rn = nb2 * 16 + b_roff;
                int cs = 2 * kb + b_cs;
                ldm_x4(bh, whb_hi + (unsigned)(rn * 128 + ((cs ^ (rn & 7)) << 4)));
                #pragma unroll
                for (int mb = 0; mb < 2; mb++) {
                    mma_f16(dacc[mb][2 * nb2],     ah[mb], bh[0], bh[1]);
                    mma_f16(dacc[mb][2 * nb2 + 1], ah[mb], bh[2], bh[3]);
                }
            }
        }
    }

    // ---- epilogue ----
    size_t rowbase = (size_t)s * BB * NN + (size_t)b * NN + i0;
    rsum[rowbase + tid] = rowsum;
    const int l4 = lane >> 2, lm4 = lane & 3;
    #pragma unroll
    for (int mb = 0; mb < 2; mb++) {
        int r0 = 32 * wid + 16 * mb + l4;
        #pragma unroll
        for (int nb = 0; nb < 8; nb++) {
            int col = 8 * nb + 2 * lm4;
            *(float2*)(part + (rowbase + r0) * FO + col)     = make_float2(dacc[mb][nb][0], dacc[mb][nb][1]);
            *(float2*)(part + (rowbase + r0 + 8) * FO + col) = make_float2(dacc[mb][nb][2], dacc[mb][nb][3]);
        }
    }
}

// ============================================================
// Kernel 3: reduce splits, normalize, relu
// ============================================================
__global__ __launch_bounds__(256)
void gat_reduce_kernel(const float* __restrict__ part,
                       const float* __restrict__ rsum,
                       float* __restrict__ out) {
    int t = blockIdx.x * blockDim.x + threadIdx.x;
    int rowi = t >> 4;
    float rs = 0.f;
    #pragma unroll
    for (int s = 0; s < SPLITS; s++) rs += rsum[(size_t)s * BB * NN + rowi];
    float inv = (rs > 0.f) ? (1.f / rs) : 0.f;
    float4 v = make_float4(0.f, 0.f, 0.f, 0.f);
    #pragma unroll
    for (int s = 0; s < SPLITS; s++) {
        float4 pv = ((const float4*)part)[(size_t)s * BB * NN * 16 + t];
        v.x += pv.x; v.y += pv.y; v.z += pv.z; v.w += pv.w;
    }
    float4 o;
    o.x = fmaxf(v.x * inv, 0.f);
    o.y = fmaxf(v.y * inv, 0.f);
    o.z = fmaxf(v.z * inv, 0.f);
    o.w = fmaxf(v.w * inv, 0.f);
    ((float4*)out)[t] = o;
}

// ============================================================
extern "C" void kernel_launch(void* const* d_in, const int* in_sizes, int n_in,
                              void* d_out, int out_size) {
    const float *h = nullptr, *adj = nullptr, *mask = nullptr, *W = nullptr, *a = nullptr;
    for (int i = 0; i < n_in; i++) {
        switch (in_sizes[i]) {
            case BB * NN * FIN:  h    = (const float*)d_in[i]; break;
            case BB * NN * NN:   adj  = (const float*)d_in[i]; break;
            case BB * NN:        mask = (const float*)d_in[i]; break;
            case FIN * FO:       W    = (const float*)d_in[i]; break;
            case 2 * FO:         a    = (const float*)d_in[i]; break;
        }
    }
    float* out = (float*)d_out;
    float* part; cudaGetSymbolAddress((void**)&part, g_part);
    float* rsum; cudaGetSymbolAddress((void**)&rsum, g_rsum);

    static bool attr_set = false;
    if (!attr_set) {
        cudaFuncSetAttribute(gat_wh_fused,  cudaFuncAttributeMaxDynamicSharedMemorySize, WH_SMEM);
        cudaFuncSetAttribute(gat_attn_hmma, cudaFuncAttributeMaxDynamicSharedMemorySize, SM_TOTAL);
        attr_set = true;
    }

    gat_wh_fused<<<BB * NN / 64, 256, WH_SMEM>>>(h, W, a, mask);
    gat_attn_hmma<<<dim3(NN / TI, BB, SPLITS), 128, SM_TOTAL>>>(adj, part, rsum);
    gat_reduce_kernel<<<BB * NN * 16 / 256, 256>>>(part, rsum, out);
}